// round 2
// baseline (speedup 1.0000x reference)
#include <cuda_runtime.h>
#include <math.h>

// Problem constants (fixed by setup_inputs): B=1, L=8192, H=16, D=64
#define H 16
#define D 64
#define L 8192
#define M 128      // L / BLKQ
#define NBLK 256   // L / BLKK
#define T 25       // int(0.1 * 256)
#define NCH 16     // chunks for kvsum partial GEMM (512 rows each)

// -------- device scratch (no allocations allowed) --------
__device__ float g_km[H*D];
__device__ float g_pq[H*M*D];
__device__ float g_pk[H*NBLK*D];
__device__ float g_score[H*M*NBLK];
__device__ int   g_lut[H*M*T];
__device__ float g_kv_part[NCH*H*D*D];
__device__ float g_ks_part[NCH*H*D];
__device__ float g_kvsum[H*D*D];
__device__ float g_ksum[H*D];

// ================= km: per-(h,d) mean of k over L =================
__global__ __launch_bounds__(256) void km_kernel(const float* __restrict__ k) {
    int h = blockIdx.x;
    __shared__ float part[256];
    int tid = threadIdx.x;
    int d = tid & 63, sub = tid >> 6;   // 4 row-substreams
    float s = 0.f;
    for (int l = sub; l < L; l += 4) s += k[(l*H + h)*D + d];
    part[tid] = s;
    __syncthreads();
    if (tid < 64) {
        float t = part[tid] + part[tid+64] + part[tid+128] + part[tid+192];
        g_km[h*D + tid] = t * (1.0f/8192.0f);
    }
}

// ========== pooled_q [h][M][D], pooled_k (centered) [h][N][D] ==========
__global__ __launch_bounds__(64) void pooled_kernel(const float* __restrict__ q,
                                                    const float* __restrict__ k) {
    int h = blockIdx.x, y = blockIdx.y, d = threadIdx.x;
    if (y < M) {
        float s = 0.f;
        for (int i = 0; i < 64; i++) s += q[((y*64 + i)*H + h)*D + d];
        g_pq[(h*M + y)*D + d] = s * (1.0f/64.0f);
    } else {
        int n = y - M;
        float s = 0.f;
        for (int i = 0; i < 32; i++) s += k[((n*32 + i)*H + h)*D + d];
        g_pk[(h*NBLK + n)*D + d] = s * (1.0f/32.0f) - g_km[h*D + d];
    }
}

// ============ routing scores: score[h][m][n] = pq . pk ============
__global__ __launch_bounds__(256) void score_kernel() {
    int h = blockIdx.x, m = blockIdx.y;
    __shared__ float pq[64];
    int tid = threadIdx.x;
    if (tid < 64) pq[tid] = g_pq[(h*M + m)*D + tid];
    __syncthreads();
    int n = tid;  // 256 threads
    const float4* pk = (const float4*)(g_pk + (h*NBLK + n)*D);
    float s = 0.f;
    #pragma unroll
    for (int dd = 0; dd < 16; dd++) {
        float4 kv = pk[dd];
        s += pq[dd*4+0]*kv.x + pq[dd*4+1]*kv.y + pq[dd*4+2]*kv.z + pq[dd*4+3]*kv.w;
    }
    g_score[(h*M + m)*NBLK + n] = s;
}

// ============ top-25 per (h,m), ties -> lowest index, sorted ascending ============
__global__ __launch_bounds__(256) void topk_kernel() {
    int h = blockIdx.x;
    int w = threadIdx.x >> 5, lane = threadIdx.x & 31;
    int m = blockIdx.y*8 + w;
    const float* row = g_score + (h*M + m)*NBLK;
    float v[8];
    #pragma unroll
    for (int j = 0; j < 8; j++) v[j] = row[j*32 + lane];
    int sel[T];
    for (int t = 0; t < T; t++) {
        float bv = -INFINITY; int bi = 1 << 30;
        #pragma unroll
        for (int j = 0; j < 8; j++) {
            if (v[j] > bv) { bv = v[j]; bi = j*32 + lane; }  // strict > : lowest index kept
        }
        #pragma unroll
        for (int off = 16; off > 0; off >>= 1) {
            float ov = __shfl_xor_sync(0xffffffffu, bv, off);
            int   oi = __shfl_xor_sync(0xffffffffu, bi, off);
            if (ov > bv || (ov == bv && oi < bi)) { bv = ov; bi = oi; }
        }
        sel[t] = bi;
        if ((bi & 31) == lane) v[bi >> 5] = -INFINITY;
    }
    if (lane == 0) {
        for (int a = 1; a < T; a++) {
            int key = sel[a]; int b = a - 1;
            while (b >= 0 && sel[b] > key) { sel[b+1] = sel[b]; b--; }
            sel[b+1] = key;
        }
        for (int t = 0; t < T; t++) g_lut[(h*M + m)*T + t] = sel[t];
    }
}

// ============ block-sparse attention, writes o_s to out ([l][h][d]) ============
__global__ __launch_bounds__(256) void sparse_attn_kernel(
    const float* __restrict__ q, const float* __restrict__ k,
    const float* __restrict__ v, float* __restrict__ out)
{
    int h = blockIdx.x, m = blockIdx.y;
    __shared__ float qs[64][68];
    __shared__ float ks[32][68];
    __shared__ float vs[32][68];
    __shared__ float ps[8][8][32];
    __shared__ float kmS[64];
    int tid = threadIdx.x;
    int w = tid >> 5, lane = tid & 31;
    if (tid < 64) kmS[tid] = g_km[h*D + tid];
    for (int i = tid; i < 64*64; i += 256) {
        int r = i >> 6, d = i & 63;
        qs[r][d] = q[((m*64 + r)*H + h)*D + d];
    }
    float mrow[8], lrow[8];
    float2 acc[8];
    #pragma unroll
    for (int j = 0; j < 8; j++) { mrow[j] = -INFINITY; lrow[j] = 0.f; acc[j] = make_float2(0.f, 0.f); }

    for (int t = 0; t < T; t++) {
        int n = g_lut[(h*M + m)*T + t];
        __syncthreads();   // protect previous-iter smem reads AND q-tile write (1st iter w/ barrier below)
        for (int i = tid; i < 32*64; i += 256) {
            int r = i >> 6, d = i & 63;
            int l = n*32 + r;
            ks[r][d] = k[(l*H + h)*D + d] - kmS[d];
            vs[r][d] = v[(l*H + h)*D + d];
        }
        __syncthreads();

        // scores: lane = key within block, register-blocked over 8 queries
        float s[8];
        #pragma unroll
        for (int j = 0; j < 8; j++) s[j] = 0.f;
        const float4* krow = (const float4*)(&ks[lane][0]);
        #pragma unroll
        for (int dd = 0; dd < 16; dd++) {
            float4 kv = krow[dd];
            #pragma unroll
            for (int j = 0; j < 8; j++) {
                float4 qv = *(const float4*)(&qs[w*8 + j][dd*4]);
                s[j] += qv.x*kv.x + qv.y*kv.y + qv.z*kv.z + qv.w*kv.w;
            }
        }
        // online softmax per query
        #pragma unroll
        for (int j = 0; j < 8; j++) {
            float sj = s[j] * 0.125f;   // 1/sqrt(64)
            float bm = sj;
            #pragma unroll
            for (int o = 16; o > 0; o >>= 1) bm = fmaxf(bm, __shfl_xor_sync(0xffffffffu, bm, o));
            float mnew  = fmaxf(mrow[j], bm);
            float alpha = __expf(mrow[j] - mnew);   // 0 on first block (exp(-inf))
            float p     = __expf(sj - mnew);
            float psum  = p;
            #pragma unroll
            for (int o = 16; o > 0; o >>= 1) psum += __shfl_xor_sync(0xffffffffu, psum, o);
            lrow[j] = lrow[j]*alpha + psum;
            mrow[j] = mnew;
            acc[j].x *= alpha; acc[j].y *= alpha;
            ps[w][j][lane] = p;
        }
        __syncwarp();
        // PV: one V smem read serves 8 queries; lane owns d = {2*lane, 2*lane+1}
        #pragma unroll
        for (int kk = 0; kk < 32; kk++) {
            float2 vv = *(const float2*)(&vs[kk][2*lane]);
            #pragma unroll
            for (int j = 0; j < 8; j++) {
                float p = ps[w][j][kk];
                acc[j].x += p*vv.x; acc[j].y += p*vv.y;
            }
        }
    }
    #pragma unroll
    for (int j = 0; j < 8; j++) {
        int l = m*64 + w*8 + j;
        float inv = 1.f / lrow[j];
        float2 o2 = make_float2(acc[j].x*inv, acc[j].y*inv);
        *(float2*)(out + (l*H + h)*D + 2*lane) = o2;
    }
}

// ====== kvsum partials: kv[h][d][e] = sum_l softmax_d(k[l,h,:])[d] * v[l,h,e] ======
__global__ __launch_bounds__(256) void kvsum_partial_kernel(const float* __restrict__ k,
                                                            const float* __restrict__ v) {
    int h = blockIdx.x, c = blockIdx.y;   // NCH chunks of 512 rows
    __shared__ float kfS[8][64];
    __shared__ float vS[8][64];
    int tid = threadIdx.x, w = tid >> 5, lane = tid & 31;
    int e = tid & 63, g = tid >> 6;       // 4 d-groups of 16
    int d0 = g * 16;
    float acc[16];
    #pragma unroll
    for (int j = 0; j < 16; j++) acc[j] = 0.f;
    float ks_acc = 0.f;

    for (int sIt = 0; sIt < 64; sIt++) {
        int l = c*512 + sIt*8 + w;
        __syncthreads();
        const float* kr = k + (l*H + h)*D;
        const float* vr = v + (l*H + h)*D;
        float k0 = kr[lane], k1 = kr[lane + 32];
        float mx = fmaxf(k0, k1);
        #pragma unroll
        for (int o = 16; o > 0; o >>= 1) mx = fmaxf(mx, __shfl_xor_sync(0xffffffffu, mx, o));
        float e0 = __expf(k0 - mx), e1 = __expf(k1 - mx);
        float sm = e0 + e1;
        #pragma unroll
        for (int o = 16; o > 0; o >>= 1) sm += __shfl_xor_sync(0xffffffffu, sm, o);
        float inv = 1.f / sm;
        kfS[w][lane] = e0*inv; kfS[w][lane+32] = e1*inv;
        vS[w][lane] = vr[lane]; vS[w][lane+32] = vr[lane+32];
        __syncthreads();
        #pragma unroll
        for (int r = 0; r < 8; r++) {
            float ve = vS[r][e];
            #pragma unroll
            for (int j = 0; j < 16; j++) acc[j] += kfS[r][d0 + j] * ve;
        }
        if (g == 0) {
            #pragma unroll
            for (int r = 0; r < 8; r++) ks_acc += kfS[r][e];
        }
    }
    float* dst = g_kv_part + (c*H + h)*D*D;
    #pragma unroll
    for (int j = 0; j < 16; j++) dst[(d0 + j)*D + e] = acc[j];
    if (g == 0) g_ks_part[(c*H + h)*D + e] = ks_acc;
}

__global__ __launch_bounds__(256) void reduce_kv_kernel() {
    int h = blockIdx.x;
    for (int i = threadIdx.x; i < D*D; i += 256) {
        float s = 0.f;
        for (int c = 0; c < NCH; c++) s += g_kv_part[(c*H + h)*D*D + i];
        g_kvsum[h*D*D + i] = s;
    }
    for (int i = threadIdx.x; i < D; i += 256) {
        float s = 0.f;
        for (int c = 0; c < NCH; c++) s += g_ks_part[(c*H + h)*D + i];
        g_ksum[h*D + i] = s;
    }
}

// ======== linear branch output: out += (q_fm @ kvsum / denom) @ W^T + b ========
__global__ __launch_bounds__(256) void linear_out_kernel(const float* __restrict__ q,
                                                         const float* __restrict__ W,
                                                         const float* __restrict__ b,
                                                         float* __restrict__ out) {
    int h = blockIdx.x, chunk = blockIdx.y;  // 64 chunks of 128 rows
    __shared__ float kvS[64][64];
    __shared__ float WS[64][65];
    __shared__ float ksS[64];
    __shared__ float bS[64];
    __shared__ float qfmS[8][64];
    __shared__ float tmpS[8][64];
    int tid = threadIdx.x, w = tid >> 5, lane = tid & 31;
    for (int i = tid; i < 4096; i += 256) kvS[i >> 6][i & 63] = g_kvsum[h*D*D + i];
    for (int i = tid; i < 4096; i += 256) WS[i >> 6][i & 63] = W[i];
    if (tid < 64) { ksS[tid] = g_ksum[h*D + tid]; bS[tid] = b[tid]; }
    __syncthreads();

    for (int rr = 0; rr < 16; rr++) {
        int l = chunk*128 + rr*8 + w;
        const float* qr = q + (l*H + h)*D;
        float q0 = qr[lane], q1 = qr[lane + 32];
        float mx = fmaxf(q0, q1);
        #pragma unroll
        for (int o = 16; o > 0; o >>= 1) mx = fmaxf(mx, __shfl_xor_sync(0xffffffffu, mx, o));
        float e0 = __expf(q0 - mx), e1 = __expf(q1 - mx);
        float ssum = e0 + e1;
        #pragma unroll
        for (int o = 16; o > 0; o >>= 1) ssum += __shfl_xor_sync(0xffffffffu, ssum, o);
        float inv = 1.f / ssum;
        float f0 = e0*inv, f1 = e1*inv;
        qfmS[w][lane] = f0; qfmS[w][lane+32] = f1;
        float dn = f0*ksS[lane] + f1*ksS[lane+32];
        #pragma unroll
        for (int o = 16; o > 0; o >>= 1) dn += __shfl_xor_sync(0xffffffffu, dn, o);
        dn += 1e-6f;
        __syncwarp();
        float t0 = 0.f, t1 = 0.f;
        #pragma unroll
        for (int d = 0; d < 64; d++) {
            float qf = qfmS[w][d];
            t0 += qf * kvS[d][lane];
            t1 += qf * kvS[d][lane + 32];
        }
        float invdn = 1.f / dn;
        tmpS[w][lane] = t0*invdn; tmpS[w][lane+32] = t1*invdn;
        __syncwarp();
        float o0 = bS[lane], o1 = bS[lane + 32];
        #pragma unroll
        for (int e = 0; e < 64; e++) {
            float tv = tmpS[w][e];
            o0 += tv * WS[lane][e];
            o1 += tv * WS[lane + 32][e];
        }
        float* op = out + (l*H + h)*D;
        op[lane]      += o0;
        op[lane + 32] += o1;
    }
}

extern "C" void kernel_launch(void* const* d_in, const int* in_sizes, int n_in,
                              void* d_out, int out_size) {
    const float* q = (const float*)d_in[0];
    const float* k = (const float*)d_in[1];
    const float* v = (const float*)d_in[2];
    const float* W = (const float*)d_in[3];
    const float* b = (const float*)d_in[4];
    float* out = (float*)d_out;

    km_kernel<<<H, 256>>>(k);
    pooled_kernel<<<dim3(H, M + NBLK), 64>>>(q, k);
    score_kernel<<<dim3(H, M), 256>>>();
    topk_kernel<<<dim3(H, M/8), 256>>>();
    sparse_attn_kernel<<<dim3(H, M), 256>>>(q, k, v, out);
    kvsum_partial_kernel<<<dim3(H, NCH), 256>>>(k, v);
    reduce_kv_kernel<<<H, 256>>>();
    linear_out_kernel<<<dim3(H, 64), 256>>>(q, W, b, out);
}

// round 4
// speedup vs baseline: 1.8325x; 1.8325x over previous
#include <cuda_runtime.h>
#include <cuda_bf16.h>
#include <math.h>
#include <stdint.h>

#define H 16
#define D 64
#define L 8192
#define M 128
#define NBLK 256
#define T 25
#define NCH 16

__device__ float g_km[H*D];
__device__ float g_pq[H*M*D];
__device__ float g_pk[H*NBLK*D];
__device__ float g_score[H*M*NBLK];
__device__ int   g_lut[H*M*T];
__device__ float g_kv_part[NCH*H*D*D];
__device__ float g_ks_part[NCH*H*D];
__device__ float g_kvsum[H*D*D];
__device__ float g_ksum[H*D];

// ---------------- helpers ----------------
__device__ __forceinline__ void mma16816(float* c, const uint32_t* a, uint32_t b0, uint32_t b1) {
    asm volatile(
        "mma.sync.aligned.m16n8k16.row.col.f32.bf16.bf16.f32 "
        "{%0,%1,%2,%3}, {%4,%5,%6,%7}, {%8,%9}, {%0,%1,%2,%3};"
        : "+f"(c[0]), "+f"(c[1]), "+f"(c[2]), "+f"(c[3])
        : "r"(a[0]), "r"(a[1]), "r"(a[2]), "r"(a[3]), "r"(b0), "r"(b1));
}
// pack (a,b) -> bf16x2 hi and lo-residual bf16x2 (a in low half)
__device__ __forceinline__ void split_pair(float a, float b, uint32_t& hi, uint32_t& lo) {
    __nv_bfloat16 ha = __float2bfloat16(a);
    __nv_bfloat16 hb = __float2bfloat16(b);
    __nv_bfloat162 hp; hp.x = ha; hp.y = hb;
    __nv_bfloat162 lp; lp.x = __float2bfloat16(a - __bfloat162float(ha));
    lp.y = __float2bfloat16(b - __bfloat162float(hb));
    hi = *(uint32_t*)&hp; lo = *(uint32_t*)&lp;
}
__device__ __forceinline__ void split_one(float a, __nv_bfloat16& hi, __nv_bfloat16& lo) {
    hi = __float2bfloat16(a);
    lo = __float2bfloat16(a - __bfloat162float(hi));
}

// ================= aux kernels (unchanged, passing) =================
__global__ __launch_bounds__(256) void km_kernel(const float* __restrict__ k) {
    int h = blockIdx.x;
    __shared__ float part[256];
    int tid = threadIdx.x;
    int d = tid & 63, sub = tid >> 6;
    float s = 0.f;
    for (int l = sub; l < L; l += 4) s += k[(l*H + h)*D + d];
    part[tid] = s;
    __syncthreads();
    if (tid < 64) {
        float t = part[tid] + part[tid+64] + part[tid+128] + part[tid+192];
        g_km[h*D + tid] = t * (1.0f/8192.0f);
    }
}
__global__ __launch_bounds__(64) void pooled_kernel(const float* __restrict__ q,
                                                    const float* __restrict__ k) {
    int h = blockIdx.x, y = blockIdx.y, d = threadIdx.x;
    if (y < M) {
        float s = 0.f;
        for (int i = 0; i < 64; i++) s += q[((y*64 + i)*H + h)*D + d];
        g_pq[(h*M + y)*D + d] = s * (1.0f/64.0f);
    } else {
        int n = y - M;
        float s = 0.f;
        for (int i = 0; i < 32; i++) s += k[((n*32 + i)*H + h)*D + d];
        g_pk[(h*NBLK + n)*D + d] = s * (1.0f/32.0f) - g_km[h*D + d];
    }
}
__global__ __launch_bounds__(256) void score_kernel() {
    int h = blockIdx.x, m = blockIdx.y;
    __shared__ float pq[64];
    int tid = threadIdx.x;
    if (tid < 64) pq[tid] = g_pq[(h*M + m)*D + tid];
    __syncthreads();
    const float4* pk = (const float4*)(g_pk + (h*NBLK + tid)*D);
    float s = 0.f;
    #pragma unroll
    for (int dd = 0; dd < 16; dd++) {
        float4 kv = pk[dd];
        s += pq[dd*4+0]*kv.x + pq[dd*4+1]*kv.y + pq[dd*4+2]*kv.z + pq[dd*4+3]*kv.w;
    }
    g_score[(h*M + m)*NBLK + tid] = s;
}
__global__ __launch_bounds__(256) void topk_kernel() {
    int h = blockIdx.x;
    int w = threadIdx.x >> 5, lane = threadIdx.x & 31;
    int m = blockIdx.y*8 + w;
    const float* row = g_score + (h*M + m)*NBLK;
    float v[8];
    #pragma unroll
    for (int j = 0; j < 8; j++) v[j] = row[j*32 + lane];
    int sel[T];
    for (int t = 0; t < T; t++) {
        float bv = -INFINITY; int bi = 1 << 30;
        #pragma unroll
        for (int j = 0; j < 8; j++)
            if (v[j] > bv) { bv = v[j]; bi = j*32 + lane; }
        #pragma unroll
        for (int off = 16; off > 0; off >>= 1) {
            float ov = __shfl_xor_sync(0xffffffffu, bv, off);
            int   oi = __shfl_xor_sync(0xffffffffu, bi, off);
            if (ov > bv || (ov == bv && oi < bi)) { bv = ov; bi = oi; }
        }
        sel[t] = bi;
        if ((bi & 31) == lane) v[bi >> 5] = -INFINITY;
    }
    if (lane == 0) {
        for (int a = 1; a < T; a++) {
            int key = sel[a]; int b = a - 1;
            while (b >= 0 && sel[b] > key) { sel[b+1] = sel[b]; b--; }
            sel[b+1] = key;
        }
        for (int t = 0; t < T; t++) g_lut[(h*M + m)*T + t] = sel[t];
    }
}

// ============ block-sparse attention via mma.sync bf16 split ============
// grid (H, M), 128 threads (4 warps, each owns 16 query rows)
#define PADK 72   // K smem row elems (144 B)
#define PADV 40   // Vt smem row elems (80 B)

__global__ __launch_bounds__(128) void sparse_attn_mma(
    const float* __restrict__ q, const float* __restrict__ k,
    const float* __restrict__ v, float* __restrict__ out)
{
    __shared__ __align__(16) __nv_bfloat16 Kh[32*PADK];
    __shared__ __align__(16) __nv_bfloat16 Kl[32*PADK];
    __shared__ __align__(16) __nv_bfloat16 Vth[64*PADV];
    __shared__ __align__(16) __nv_bfloat16 Vtl[64*PADV];

    const int h = blockIdx.x, m = blockIdx.y;
    const int tid = threadIdx.x;
    const int w = tid >> 5, lane = tid & 31;
    const int g = lane >> 2, tc = lane & 3;

    // ---- Q fragments (persistent) ----
    // a0:(row g, col 2tc) a1:(row g+8, col 2tc) a2:(row g, col 2tc+8) a3:(row g+8, col 2tc+8)
    uint32_t aQh[4][4], aQl[4][4];
    {
        int r0 = m*64 + w*16 + g;
        int r1 = r0 + 8;
        const float* q0 = q + (r0*H + h)*D;
        const float* q1 = q + (r1*H + h)*D;
        #pragma unroll
        for (int kt = 0; kt < 4; kt++) {
            int c0 = kt*16 + tc*2;
            float2 f;
            f = *(const float2*)(q0 + c0);     split_pair(f.x, f.y, aQh[kt][0], aQl[kt][0]);
            f = *(const float2*)(q1 + c0);     split_pair(f.x, f.y, aQh[kt][1], aQl[kt][1]);
            f = *(const float2*)(q0 + c0 + 8); split_pair(f.x, f.y, aQh[kt][2], aQl[kt][2]);
            f = *(const float2*)(q1 + c0 + 8); split_pair(f.x, f.y, aQh[kt][3], aQl[kt][3]);
        }
    }

    // K loader map: key kr = tid>>2, dims kp*16..kp*16+15
    const int kr = tid >> 2, kp = tid & 3;
    float kmr[16];
    #pragma unroll
    for (int i = 0; i < 16; i++) kmr[i] = g_km[h*D + kp*16 + i];
    // V loader map: key vkey = tid&31, dims vdg*16..+15
    const int vkey = tid & 31, vdg = tid >> 5;

    float o[8][4];
    #pragma unroll
    for (int a = 0; a < 8; a++)
        #pragma unroll
        for (int j = 0; j < 4; j++) o[a][j] = 0.f;
    float lrow0 = 0.f, lrow1 = 0.f;

    for (int t = 0; t < T; t++) {
        int n = g_lut[(h*M + m)*T + t];
        __syncthreads();   // previous-iter smem reads done
        // ---- K tile: center + split -> Kh/Kl [key][dim] ----
        {
            const float4* src = (const float4*)(k + ((n*32 + kr)*H + h)*D + kp*16);
            float xs[16];
            #pragma unroll
            for (int i = 0; i < 4; i++) {
                float4 f = src[i];
                xs[4*i+0]=f.x-kmr[4*i+0]; xs[4*i+1]=f.y-kmr[4*i+1];
                xs[4*i+2]=f.z-kmr[4*i+2]; xs[4*i+3]=f.w-kmr[4*i+3];
            }
            uint32_t hi[8], lo[8];
            #pragma unroll
            for (int j = 0; j < 8; j++) split_pair(xs[2*j], xs[2*j+1], hi[j], lo[j]);
            uint4* dh = (uint4*)(Kh + kr*PADK + kp*16);
            uint4* dl = (uint4*)(Kl + kr*PADK + kp*16);
            dh[0] = make_uint4(hi[0],hi[1],hi[2],hi[3]);
            dh[1] = make_uint4(hi[4],hi[5],hi[6],hi[7]);
            dl[0] = make_uint4(lo[0],lo[1],lo[2],lo[3]);
            dl[1] = make_uint4(lo[4],lo[5],lo[6],lo[7]);
        }
        // ---- V tile: split -> transposed Vth/Vtl [dim][key] ----
        {
            const float4* src = (const float4*)(v + ((n*32 + vkey)*H + h)*D + vdg*16);
            #pragma unroll
            for (int i = 0; i < 4; i++) {
                float4 f = src[i];
                float xs[4] = {f.x, f.y, f.z, f.w};
                #pragma unroll
                for (int jj = 0; jj < 4; jj++) {
                    __nv_bfloat16 hb, lb;
                    split_one(xs[jj], hb, lb);
                    int dd = vdg*16 + i*4 + jj;
                    Vth[dd*PADV + vkey] = hb;
                    Vtl[dd*PADV + vkey] = lb;
                }
            }
        }
        __syncthreads();

        // ---- QK: S[16q x 32k] per warp, split 3-pass ----
        float c[4][4];
        #pragma unroll
        for (int nt = 0; nt < 4; nt++)
            #pragma unroll
            for (int j = 0; j < 4; j++) c[nt][j] = 0.f;
        #pragma unroll
        for (int kt = 0; kt < 4; kt++) {
            #pragma unroll
            for (int nt = 0; nt < 4; nt++) {
                const __nv_bfloat16* bh = Kh + (nt*8 + g)*PADK + kt*16 + tc*2;
                const __nv_bfloat16* bl = Kl + (nt*8 + g)*PADK + kt*16 + tc*2;
                uint32_t bh0 = *(const uint32_t*)bh;
                uint32_t bh1 = *(const uint32_t*)(bh + 8);
                uint32_t bl0 = *(const uint32_t*)bl;
                uint32_t bl1 = *(const uint32_t*)(bl + 8);
                mma16816(c[nt], aQh[kt], bh0, bh1);
                mma16816(c[nt], aQl[kt], bh0, bh1);
                mma16816(c[nt], aQh[kt], bl0, bl1);
            }
        }
        // ---- exp (no max-sub; scores/8 ~ N(0,1)) + row sums ----
        float pr[4][4];
        float rs0 = 0.f, rs1 = 0.f;
        #pragma unroll
        for (int nt = 0; nt < 4; nt++) {
            #pragma unroll
            for (int j = 0; j < 4; j++) pr[nt][j] = __expf(c[nt][j] * 0.125f);
            rs0 += pr[nt][0] + pr[nt][1];
            rs1 += pr[nt][2] + pr[nt][3];
        }
        rs0 += __shfl_xor_sync(0xffffffffu, rs0, 1);
        rs0 += __shfl_xor_sync(0xffffffffu, rs0, 2);
        rs1 += __shfl_xor_sync(0xffffffffu, rs1, 1);
        rs1 += __shfl_xor_sync(0xffffffffu, rs1, 2);
        lrow0 += rs0; lrow1 += rs1;

        // ---- P fragments (c-layout -> a-layout correspondence) ----
        uint32_t aPh[2][4], aPl[2][4];
        #pragma unroll
        for (int kp2 = 0; kp2 < 2; kp2++) {
            split_pair(pr[2*kp2][0],   pr[2*kp2][1],   aPh[kp2][0], aPl[kp2][0]);
            split_pair(pr[2*kp2][2],   pr[2*kp2][3],   aPh[kp2][1], aPl[kp2][1]);
            split_pair(pr[2*kp2+1][0], pr[2*kp2+1][1], aPh[kp2][2], aPl[kp2][2]);
            split_pair(pr[2*kp2+1][2], pr[2*kp2+1][3], aPh[kp2][3], aPl[kp2][3]);
        }
        // ---- PV: O[16q x 64d] += P x V ----
        #pragma unroll
        for (int kp2 = 0; kp2 < 2; kp2++) {
            #pragma unroll
            for (int nv = 0; nv < 8; nv++) {
                const __nv_bfloat16* bh = Vth + (nv*8 + g)*PADV + kp2*16 + tc*2;
                const __nv_bfloat16* bl = Vtl + (nv*8 + g)*PADV + kp2*16 + tc*2;
                uint32_t bh0 = *(const uint32_t*)bh;
                uint32_t bh1 = *(const uint32_t*)(bh + 8);
                uint32_t bl0 = *(const uint32_t*)bl;
                uint32_t bl1 = *(const uint32_t*)(bl + 8);
                mma16816(o[nv], aPh[kp2], bh0, bh1);
                mma16816(o[nv], aPl[kp2], bh0, bh1);
                mma16816(o[nv], aPh[kp2], bl0, bl1);
            }
        }
    }

    // ---- epilogue: divide by row sums, store ----
    float inv0 = 1.f / lrow0;
    float inv1 = 1.f / lrow1;
    int r0 = m*64 + w*16 + g;
    float* out0 = out + (r0*H + h)*D;
    float* out1 = out + ((r0+8)*H + h)*D;
    #pragma unroll
    for (int nv = 0; nv < 8; nv++) {
        int cc = nv*8 + tc*2;
        *(float2*)(out0 + cc) = make_float2(o[nv][0]*inv0, o[nv][1]*inv0);
        *(float2*)(out1 + cc) = make_float2(o[nv][2]*inv1, o[nv][3]*inv1);
    }
}

// ====== kvsum partials ======
__global__ __launch_bounds__(256) void kvsum_partial_kernel(const float* __restrict__ k,
                                                            const float* __restrict__ v) {
    int h = blockIdx.x, c = blockIdx.y;
    __shared__ float kfS[8][64];
    __shared__ float vS[8][64];
    int tid = threadIdx.x, w = tid >> 5, lane = tid & 31;
    int e = tid & 63, g = tid >> 6;
    int d0 = g * 16;
    float acc[16];
    #pragma unroll
    for (int j = 0; j < 16; j++) acc[j] = 0.f;
    float ks_acc = 0.f;
    for (int sIt = 0; sIt < 64; sIt++) {
        int l = c*512 + sIt*8 + w;
        __syncthreads();
        const float* kr = k + (l*H + h)*D;
        const float* vr = v + (l*H + h)*D;
        float k0 = kr[lane], k1 = kr[lane + 32];
        float mx = fmaxf(k0, k1);
        #pragma unroll
        for (int o = 16; o > 0; o >>= 1) mx = fmaxf(mx, __shfl_xor_sync(0xffffffffu, mx, o));
        float e0 = __expf(k0 - mx), e1 = __expf(k1 - mx);
        float sm = e0 + e1;
        #pragma unroll
        for (int o = 16; o > 0; o >>= 1) sm += __shfl_xor_sync(0xffffffffu, sm, o);
        float inv = 1.f / sm;
        kfS[w][lane] = e0*inv; kfS[w][lane+32] = e1*inv;
        vS[w][lane] = vr[lane]; vS[w][lane+32] = vr[lane+32];
        __syncthreads();
        #pragma unroll
        for (int rr = 0; rr < 8; rr++) {
            float ve = vS[rr][e];
            #pragma unroll
            for (int j = 0; j < 16; j++) acc[j] += kfS[rr][d0 + j] * ve;
        }
        if (g == 0) {
            #pragma unroll
            for (int rr = 0; rr < 8; rr++) ks_acc += kfS[rr][e];
        }
    }
    float* dst = g_kv_part + (c*H + h)*D*D;
    #pragma unroll
    for (int j = 0; j < 16; j++) dst[(d0 + j)*D + e] = acc[j];
    if (g == 0) g_ks_part[(c*H + h)*D + e] = ks_acc;
}
__global__ __launch_bounds__(256) void reduce_kv_kernel() {
    int h = blockIdx.x;
    for (int i = threadIdx.x; i < D*D; i += 256) {
        float s = 0.f;
        for (int c = 0; c < NCH; c++) s += g_kv_part[(c*H + h)*D*D + i];
        g_kvsum[h*D*D + i] = s;
    }
    for (int i = threadIdx.x; i < D; i += 256) {
        float s = 0.f;
        for (int c = 0; c < NCH; c++) s += g_ks_part[(c*H + h)*D + i];
        g_ksum[h*D + i] = s;
    }
}
__global__ __launch_bounds__(256) void linear_out_kernel(const float* __restrict__ q,
                                                         const float* __restrict__ W,
                                                         const float* __restrict__ b,
                                                         float* __restrict__ out) {
    int h = blockIdx.x, chunk = blockIdx.y;
    __shared__ float kvS[64][64];
    __shared__ float WS[64][65];
    __shared__ float ksS[64];
    __shared__ float bS[64];
    __shared__ float qfmS[8][64];
    __shared__ float tmpS[8][64];
    int tid = threadIdx.x, w = tid >> 5, lane = tid & 31;
    for (int i = tid; i < 4096; i += 256) kvS[i >> 6][i & 63] = g_kvsum[h*D*D + i];
    for (int i = tid; i < 4096; i += 256) WS[i >> 6][i & 63] = W[i];
    if (tid < 64) { ksS[tid] = g_ksum[h*D + tid]; bS[tid] = b[tid]; }
    __syncthreads();
    for (int rr = 0; rr < 16; rr++) {
        int l = chunk*128 + rr*8 + w;
        const float* qr = q + (l*H + h)*D;
        float q0 = qr[lane], q1 = qr[lane + 32];
        float mx = fmaxf(q0, q1);
        #pragma unroll
        for (int o = 16; o > 0; o >>= 1) mx = fmaxf(mx, __shfl_xor_sync(0xffffffffu, mx, o));
        float e0 = __expf(q0 - mx), e1 = __expf(q1 - mx);
        float ssum = e0 + e1;
        #pragma unroll
        for (int o = 16; o > 0; o >>= 1) ssum += __shfl_xor_sync(0xffffffffu, ssum, o);
        float inv = 1.f / ssum;
        float f0 = e0*inv, f1 = e1*inv;
        qfmS[w][lane] = f0; qfmS[w][lane+32] = f1;
        float dn = f0*ksS[lane] + f1*ksS[lane+32];
        #pragma unroll
        for (int o = 16; o > 0; o >>= 1) dn += __shfl_xor_sync(0xffffffffu, dn, o);
        dn += 1e-6f;
        __syncwarp();
        float t0 = 0.f, t1 = 0.f;
        #pragma unroll
        for (int d = 0; d < 64; d++) {
            float qf = qfmS[w][d];
            t0 += qf * kvS[d][lane];
            t1 += qf * kvS[d][lane + 32];
        }
        float invdn = 1.f / dn;
        tmpS[w][lane] = t0*invdn; tmpS[w][lane+32] = t1*invdn;
        __syncwarp();
        float o0 = bS[lane], o1 = bS[lane + 32];
        #pragma unroll
        for (int e = 0; e < 64; e++) {
            float tv = tmpS[w][e];
            o0 += tv * WS[lane][e];
            o1 += tv * WS[lane + 32][e];
        }
        float* op = out + (l*H + h)*D;
        op[lane]      += o0;
        op[lane + 32] += o1;
    }
}

extern "C" void kernel_launch(void* const* d_in, const int* in_sizes, int n_in,
                              void* d_out, int out_size) {
    const float* q = (const float*)d_in[0];
    const float* k = (const float*)d_in[1];
    const float* v = (const float*)d_in[2];
    const float* W = (const float*)d_in[3];
    const float* b = (const float*)d_in[4];
    float* out = (float*)d_out;

    km_kernel<<<H, 256>>>(k);
    pooled_kernel<<<dim3(H, M + NBLK), 64>>>(q, k);
    score_kernel<<<dim3(H, M), 256>>>();
    topk_kernel<<<dim3(H, M/8), 256>>>();
    sparse_attn_mma<<<dim3(H, M), 128>>>(q, k, v, out);
    kvsum_partial_kernel<<<dim3(H, NCH), 256>>>(k, v);
    reduce_kv_kernel<<<H, 256>>>();
    linear_out_kernel<<<dim3(H, 64), 256>>>(q, W, b, out);
}

// round 5
// speedup vs baseline: 1.9663x; 1.0730x over previous
#include <cuda_runtime.h>
#include <cuda_bf16.h>
#include <math.h>
#include <stdint.h>

#define H 16
#define D 64
#define L 8192
#define M 128
#define NBLK 256
#define T 25
#define NCH 16

#define PADK 72   // K row elems (144 B) -> bank perm 4g+tc, conflict-free
#define PADV 40   // Vt row elems (80 B) -> bank perm 20g+tc, conflict-free

__device__ float g_km[H*D];
__device__ float g_pq[H*M*D];
__device__ float g_pk[H*NBLK*D];
__device__ float g_score[H*M*NBLK];
__device__ int   g_lut[H*M*T];
__device__ float g_kv_part[NCH*H*D*D];
__device__ float g_ks_part[NCH*H*D];
__device__ float g_kvsum[H*D*D];
__device__ float g_ksum[H*D];
// precomputed centered/split K and split/transposed V (bf16 hi/lo)
__device__ __nv_bfloat16 g_kch[(size_t)H*NBLK*32*PADK];
__device__ __nv_bfloat16 g_kcl[(size_t)H*NBLK*32*PADK];
__device__ __nv_bfloat16 g_vth[(size_t)H*NBLK*64*PADV];
__device__ __nv_bfloat16 g_vtl[(size_t)H*NBLK*64*PADV];

// ---------------- helpers ----------------
__device__ __forceinline__ uint32_t smem_u32(const void* p) {
    return (uint32_t)__cvta_generic_to_shared(p);
}
__device__ __forceinline__ void cp16(uint32_t saddr, const void* gaddr) {
    asm volatile("cp.async.cg.shared.global [%0], [%1], 16;" :: "r"(saddr), "l"(gaddr));
}
#define CP_COMMIT() asm volatile("cp.async.commit_group;" ::: "memory")
#define CP_WAIT(n)  asm volatile("cp.async.wait_group %0;" :: "n"(n) : "memory")

__device__ __forceinline__ void mma16816(float* c, const uint32_t* a, uint32_t b0, uint32_t b1) {
    asm volatile(
        "mma.sync.aligned.m16n8k16.row.col.f32.bf16.bf16.f32 "
        "{%0,%1,%2,%3}, {%4,%5,%6,%7}, {%8,%9}, {%0,%1,%2,%3};"
        : "+f"(c[0]), "+f"(c[1]), "+f"(c[2]), "+f"(c[3])
        : "r"(a[0]), "r"(a[1]), "r"(a[2]), "r"(a[3]), "r"(b0), "r"(b1));
}
__device__ __forceinline__ void split_pair(float a, float b, uint32_t& hi, uint32_t& lo) {
    __nv_bfloat16 ha = __float2bfloat16(a);
    __nv_bfloat16 hb = __float2bfloat16(b);
    __nv_bfloat162 hp; hp.x = ha; hp.y = hb;
    __nv_bfloat162 lp; lp.x = __float2bfloat16(a - __bfloat162float(ha));
    lp.y = __float2bfloat16(b - __bfloat162float(hb));
    hi = *(uint32_t*)&hp; lo = *(uint32_t*)&lp;
}

// ================= aux kernels =================
__global__ __launch_bounds__(256) void km_kernel(const float* __restrict__ k) {
    int h = blockIdx.x;
    __shared__ float part[256];
    int tid = threadIdx.x;
    int d = tid & 63, sub = tid >> 6;
    float s = 0.f;
    for (int l = sub; l < L; l += 4) s += k[(l*H + h)*D + d];
    part[tid] = s;
    __syncthreads();
    if (tid < 64) {
        float t = part[tid] + part[tid+64] + part[tid+128] + part[tid+192];
        g_km[h*D + tid] = t * (1.0f/8192.0f);
    }
}

// ===== precompute: centered+split K [32][PADK], split+transposed V [64][PADV] =====
__global__ __launch_bounds__(128) void convert_kv_kernel(const float* __restrict__ k,
                                                         const float* __restrict__ v) {
    int h = blockIdx.x, n = blockIdx.y;
    int tid = threadIdx.x;
    __shared__ float vS[32][65];

    // stage V fp32 into smem (for transpose)
    {
        int vr = tid >> 2, vp = tid & 3;
        const float4* src = (const float4*)(v + ((size_t)(n*32 + vr)*H + h)*D + vp*16);
        #pragma unroll
        for (int i = 0; i < 4; i++) {
            float4 f = src[i];
            vS[vr][vp*16 + 4*i + 0] = f.x;
            vS[vr][vp*16 + 4*i + 1] = f.y;
            vS[vr][vp*16 + 4*i + 2] = f.z;
            vS[vr][vp*16 + 4*i + 3] = f.w;
        }
    }
    // K: center + split -> gmem
    {
        int kr = tid >> 2, kp = tid & 3;
        const float4* src = (const float4*)(k + ((size_t)(n*32 + kr)*H + h)*D + kp*16);
        float xs[16];
        #pragma unroll
        for (int i = 0; i < 4; i++) {
            float4 f = src[i];
            xs[4*i+0] = f.x - g_km[h*D + kp*16 + 4*i+0];
            xs[4*i+1] = f.y - g_km[h*D + kp*16 + 4*i+1];
            xs[4*i+2] = f.z - g_km[h*D + kp*16 + 4*i+2];
            xs[4*i+3] = f.w - g_km[h*D + kp*16 + 4*i+3];
        }
        uint32_t hi[8], lo[8];
        #pragma unroll
        for (int j = 0; j < 8; j++) split_pair(xs[2*j], xs[2*j+1], hi[j], lo[j]);
        size_t off = ((size_t)(h*NBLK + n)*32 + kr)*PADK + kp*16;
        *(uint4*)(g_kch + off)     = make_uint4(hi[0],hi[1],hi[2],hi[3]);
        *(uint4*)(g_kch + off + 8) = make_uint4(hi[4],hi[5],hi[6],hi[7]);
        *(uint4*)(g_kcl + off)     = make_uint4(lo[0],lo[1],lo[2],lo[3]);
        *(uint4*)(g_kcl + off + 8) = make_uint4(lo[4],lo[5],lo[6],lo[7]);
    }
    __syncthreads();
    // V: transpose + split -> gmem [dim][key]
    {
        int d = tid & 63, part = tid >> 6;  // part: keys 0-15 / 16-31
        uint32_t hi[8], lo[8];
        #pragma unroll
        for (int j = 0; j < 8; j++) {
            float a = vS[part*16 + 2*j][d];
            float b = vS[part*16 + 2*j + 1][d];
            split_pair(a, b, hi[j], lo[j]);
        }
        size_t off = ((size_t)(h*NBLK + n)*64 + d)*PADV + part*16;
        *(uint4*)(g_vth + off)     = make_uint4(hi[0],hi[1],hi[2],hi[3]);
        *(uint4*)(g_vth + off + 8) = make_uint4(hi[4],hi[5],hi[6],hi[7]);
        *(uint4*)(g_vtl + off)     = make_uint4(lo[0],lo[1],lo[2],lo[3]);
        *(uint4*)(g_vtl + off + 8) = make_uint4(lo[4],lo[5],lo[6],lo[7]);
    }
}

__global__ __launch_bounds__(64) void pooled_kernel(const float* __restrict__ q,
                                                    const float* __restrict__ k) {
    int h = blockIdx.x, y = blockIdx.y, d = threadIdx.x;
    if (y < M) {
        float s = 0.f;
        for (int i = 0; i < 64; i++) s += q[((y*64 + i)*H + h)*D + d];
        g_pq[(h*M + y)*D + d] = s * (1.0f/64.0f);
    } else {
        int n = y - M;
        float s = 0.f;
        for (int i = 0; i < 32; i++) s += k[((n*32 + i)*H + h)*D + d];
        g_pk[(h*NBLK + n)*D + d] = s * (1.0f/32.0f) - g_km[h*D + d];
    }
}
__global__ __launch_bounds__(256) void score_kernel() {
    int h = blockIdx.x, m = blockIdx.y;
    __shared__ float pq[64];
    int tid = threadIdx.x;
    if (tid < 64) pq[tid] = g_pq[(h*M + m)*D + tid];
    __syncthreads();
    const float4* pk = (const float4*)(g_pk + (h*NBLK + tid)*D);
    float s = 0.f;
    #pragma unroll
    for (int dd = 0; dd < 16; dd++) {
        float4 kv = pk[dd];
        s += pq[dd*4+0]*kv.x + pq[dd*4+1]*kv.y + pq[dd*4+2]*kv.z + pq[dd*4+3]*kv.w;
    }
    g_score[(h*M + m)*NBLK + tid] = s;
}
__global__ __launch_bounds__(256) void topk_kernel() {
    int h = blockIdx.x;
    int w = threadIdx.x >> 5, lane = threadIdx.x & 31;
    int m = blockIdx.y*8 + w;
    const float* row = g_score + (h*M + m)*NBLK;
    float v[8];
    #pragma unroll
    for (int j = 0; j < 8; j++) v[j] = row[j*32 + lane];
    int sel[T];
    for (int t = 0; t < T; t++) {
        float bv = -INFINITY; int bi = 1 << 30;
        #pragma unroll
        for (int j = 0; j < 8; j++)
            if (v[j] > bv) { bv = v[j]; bi = j*32 + lane; }
        #pragma unroll
        for (int off = 16; off > 0; off >>= 1) {
            float ov = __shfl_xor_sync(0xffffffffu, bv, off);
            int   oi = __shfl_xor_sync(0xffffffffu, bi, off);
            if (ov > bv || (ov == bv && oi < bi)) { bv = ov; bi = oi; }
        }
        sel[t] = bi;
        if ((bi & 31) == lane) v[bi >> 5] = -INFINITY;
    }
    if (lane == 0) {
        for (int a = 1; a < T; a++) {
            int key = sel[a]; int b = a - 1;
            while (b >= 0 && sel[b] > key) { sel[b+1] = sel[b]; b--; }
            sel[b+1] = key;
        }
        for (int t = 0; t < T; t++) g_lut[(h*M + m)*T + t] = sel[t];
    }
}

// ============ block-sparse attention: cp.async double-buffer + mma.sync ============
__global__ __launch_bounds__(128) void sparse_attn_mma(
    const float* __restrict__ q, float* __restrict__ out)
{
    __shared__ __align__(16) __nv_bfloat16 sKh[2][32*PADK];
    __shared__ __align__(16) __nv_bfloat16 sKl[2][32*PADK];
    __shared__ __align__(16) __nv_bfloat16 sVh[2][64*PADV];
    __shared__ __align__(16) __nv_bfloat16 sVl[2][64*PADV];

    const int h = blockIdx.x, m = blockIdx.y;
    const int tid = threadIdx.x;
    const int w = tid >> 5, lane = tid & 31;
    const int g = lane >> 2, tc = lane & 3;

    // ---- Q fragments (persistent, from fp32 gmem, split) ----
    uint32_t aQh[4][4], aQl[4][4];
    {
        int r0 = m*64 + w*16 + g;
        const float* q0 = q + ((size_t)r0*H + h)*D;
        const float* q1 = q + ((size_t)(r0+8)*H + h)*D;
        #pragma unroll
        for (int kt = 0; kt < 4; kt++) {
            int c0 = kt*16 + tc*2;
            float2 f;
            f = *(const float2*)(q0 + c0);     split_pair(f.x, f.y, aQh[kt][0], aQl[kt][0]);
            f = *(const float2*)(q1 + c0);     split_pair(f.x, f.y, aQh[kt][1], aQl[kt][1]);
            f = *(const float2*)(q0 + c0 + 8); split_pair(f.x, f.y, aQh[kt][2], aQl[kt][2]);
            f = *(const float2*)(q1 + c0 + 8); split_pair(f.x, f.y, aQh[kt][3], aQl[kt][3]);
        }
    }

    // loader maps
    const int krow = tid >> 2, kseg = tid & 3;    // K: 32B per thread per tile
    const int vrow = tid >> 1, vseg = tid & 1;    // V: 32B per thread per tile
    const uint32_t ksm = (uint32_t)(krow*PADK + kseg*16)*2;
    const uint32_t vsm = (uint32_t)(vrow*PADV + vseg*16)*2;
    const size_t   kgo = (size_t)krow*PADK + kseg*16;
    const size_t   vgo = (size_t)vrow*PADV + vseg*16;
    const int* lut = g_lut + (h*M + m)*T;

    #define LOAD_STAGE(n_, buf_) do { \
        size_t kb = ((size_t)(h*NBLK + (n_)))*32*PADK + kgo; \
        size_t vb = ((size_t)(h*NBLK + (n_)))*64*PADV + vgo; \
        uint32_t skh = smem_u32(&sKh[buf_][0]) + ksm; \
        uint32_t skl = smem_u32(&sKl[buf_][0]) + ksm; \
        uint32_t svh = smem_u32(&sVh[buf_][0]) + vsm; \
        uint32_t svl = smem_u32(&sVl[buf_][0]) + vsm; \
        cp16(skh,      g_kch + kb); \
        cp16(skh + 16, g_kch + kb + 8); \
        cp16(skl,      g_kcl + kb); \
        cp16(skl + 16, g_kcl + kb + 8); \
        cp16(svh,      g_vth + vb); \
        cp16(svh + 16, g_vth + vb + 8); \
        cp16(svl,      g_vtl + vb); \
        cp16(svl + 16, g_vtl + vb + 8); \
    } while (0)

    float o[8][4];
    #pragma unroll
    for (int a = 0; a < 8; a++)
        #pragma unroll
        for (int j = 0; j < 4; j++) o[a][j] = 0.f;
    float lrow0 = 0.f, lrow1 = 0.f;

    LOAD_STAGE(lut[0], 0);
    CP_COMMIT();

    for (int t = 0; t < T; t++) {
        int buf = t & 1;
        if (t + 1 < T) {
            LOAD_STAGE(lut[t+1], (t+1) & 1);
            CP_COMMIT();
            CP_WAIT(1);
        } else {
            CP_WAIT(0);
        }
        __syncthreads();

        const __nv_bfloat16* Kh = sKh[buf];
        const __nv_bfloat16* Kl = sKl[buf];
        const __nv_bfloat16* Vth = sVh[buf];
        const __nv_bfloat16* Vtl = sVl[buf];

        // ---- QK: S[16q x 32k], 3-pass split ----
        float c[4][4];
        #pragma unroll
        for (int nt = 0; nt < 4; nt++)
            #pragma unroll
            for (int j = 0; j < 4; j++) c[nt][j] = 0.f;
        #pragma unroll
        for (int kt = 0; kt < 4; kt++) {
            #pragma unroll
            for (int nt = 0; nt < 4; nt++) {
                const __nv_bfloat16* bh = Kh + (nt*8 + g)*PADK + kt*16 + tc*2;
                const __nv_bfloat16* bl = Kl + (nt*8 + g)*PADK + kt*16 + tc*2;
                uint32_t bh0 = *(const uint32_t*)bh;
                uint32_t bh1 = *(const uint32_t*)(bh + 8);
                uint32_t bl0 = *(const uint32_t*)bl;
                uint32_t bl1 = *(const uint32_t*)(bl + 8);
                mma16816(c[nt], aQh[kt], bh0, bh1);
                mma16816(c[nt], aQl[kt], bh0, bh1);
                mma16816(c[nt], aQh[kt], bl0, bl1);
            }
        }
        // ---- exp + row sums (no max-sub; s/8 ~ N(0,1)) ----
        float pr[4][4];
        float rs0 = 0.f, rs1 = 0.f;
        #pragma unroll
        for (int nt = 0; nt < 4; nt++) {
            #pragma unroll
            for (int j = 0; j < 4; j++) pr[nt][j] = __expf(c[nt][j] * 0.125f);
            rs0 += pr[nt][0] + pr[nt][1];
            rs1 += pr[nt][2] + pr[nt][3];
        }
        rs0 += __shfl_xor_sync(0xffffffffu, rs0, 1);
        rs0 += __shfl_xor_sync(0xffffffffu, rs0, 2);
        rs1 += __shfl_xor_sync(0xffffffffu, rs1, 1);
        rs1 += __shfl_xor_sync(0xffffffffu, rs1, 2);
        lrow0 += rs0; lrow1 += rs1;

        // ---- P fragments ----
        uint32_t aPh[2][4], aPl[2][4];
        #pragma unroll
        for (int kp2 = 0; kp2 < 2; kp2++) {
            split_pair(pr[2*kp2][0],   pr[2*kp2][1],   aPh[kp2][0], aPl[kp2][0]);
            split_pair(pr[2*kp2][2],   pr[2*kp2][3],   aPh[kp2][1], aPl[kp2][1]);
            split_pair(pr[2*kp2+1][0], pr[2*kp2+1][1], aPh[kp2][2], aPl[kp2][2]);
            split_pair(pr[2*kp2+1][2], pr[2*kp2+1][3], aPh[kp2][3], aPl[kp2][3]);
        }
        // ---- PV: O[16q x 64d] += P x V ----
        #pragma unroll
        for (int kp2 = 0; kp2 < 2; kp2++) {
            #pragma unroll
            for (int nv = 0; nv < 8; nv++) {
                const __nv_bfloat16* bh = Vth + (nv*8 + g)*PADV + kp2*16 + tc*2;
                const __nv_bfloat16* bl = Vtl + (nv*8 + g)*PADV + kp2*16 + tc*2;
                uint32_t bh0 = *(const uint32_t*)bh;
                uint32_t bh1 = *(const uint32_t*)(bh + 8);
                uint32_t bl0 = *(const uint32_t*)bl;
                uint32_t bl1 = *(const uint32_t*)(bl + 8);
                mma16816(o[nv], aPh[kp2], bh0, bh1);
                mma16816(o[nv], aPl[kp2], bh0, bh1);
                mma16816(o[nv], aPh[kp2], bl0, bl1);
            }
        }
        __syncthreads();
    }

    // ---- epilogue ----
    float inv0 = 1.f / lrow0;
    float inv1 = 1.f / lrow1;
    int r0 = m*64 + w*16 + g;
    float* out0 = out + ((size_t)r0*H + h)*D;
    float* out1 = out + ((size_t)(r0+8)*H + h)*D;
    #pragma unroll
    for (int nv = 0; nv < 8; nv++) {
        int cc = nv*8 + tc*2;
        *(float2*)(out0 + cc) = make_float2(o[nv][0]*inv0, o[nv][1]*inv0);
        *(float2*)(out1 + cc) = make_float2(o[nv][2]*inv1, o[nv][3]*inv1);
    }
    #undef LOAD_STAGE
}

// ====== kvsum partials ======
__global__ __launch_bounds__(256) void kvsum_partial_kernel(const float* __restrict__ k,
                                                            const float* __restrict__ v) {
    int h = blockIdx.x, c = blockIdx.y;
    __shared__ float kfS[8][64];
    __shared__ float vS[8][64];
    int tid = threadIdx.x, w = tid >> 5, lane = tid & 31;
    int e = tid & 63, g = tid >> 6;
    int d0 = g * 16;
    float acc[16];
    #pragma unroll
    for (int j = 0; j < 16; j++) acc[j] = 0.f;
    float ks_acc = 0.f;
    for (int sIt = 0; sIt < 64; sIt++) {
        int l = c*512 + sIt*8 + w;
        __syncthreads();
        const float* kr = k + (l*H + h)*D;
        const float* vr = v + (l*H + h)*D;
        float k0 = kr[lane], k1 = kr[lane + 32];
        float mx = fmaxf(k0, k1);
        #pragma unroll
        for (int o = 16; o > 0; o >>= 1) mx = fmaxf(mx, __shfl_xor_sync(0xffffffffu, mx, o));
        float e0 = __expf(k0 - mx), e1 = __expf(k1 - mx);
        float sm = e0 + e1;
        #pragma unroll
        for (int o = 16; o > 0; o >>= 1) sm += __shfl_xor_sync(0xffffffffu, sm, o);
        float inv = 1.f / sm;
        kfS[w][lane] = e0*inv; kfS[w][lane+32] = e1*inv;
        vS[w][lane] = vr[lane]; vS[w][lane+32] = vr[lane+32];
        __syncthreads();
        #pragma unroll
        for (int rr = 0; rr < 8; rr++) {
            float ve = vS[rr][e];
            #pragma unroll
            for (int j = 0; j < 16; j++) acc[j] += kfS[rr][d0 + j] * ve;
        }
        if (g == 0) {
            #pragma unroll
            for (int rr = 0; rr < 8; rr++) ks_acc += kfS[rr][e];
        }
    }
    float* dst = g_kv_part + (c*H + h)*D*D;
    #pragma unroll
    for (int j = 0; j < 16; j++) dst[(d0 + j)*D + e] = acc[j];
    if (g == 0) g_ks_part[(c*H + h)*D + e] = ks_acc;
}
__global__ __launch_bounds__(256) void reduce_kv_kernel() {
    int h = blockIdx.x;
    for (int i = threadIdx.x; i < D*D; i += 256) {
        float s = 0.f;
        for (int c = 0; c < NCH; c++) s += g_kv_part[(c*H + h)*D*D + i];
        g_kvsum[h*D*D + i] = s;
    }
    for (int i = threadIdx.x; i < D; i += 256) {
        float s = 0.f;
        for (int c = 0; c < NCH; c++) s += g_ks_part[(c*H + h)*D + i];
        g_ksum[h*D + i] = s;
    }
}
__global__ __launch_bounds__(256) void linear_out_kernel(const float* __restrict__ q,
                                                         const float* __restrict__ W,
                                                         const float* __restrict__ b,
                                                         float* __restrict__ out) {
    int h = blockIdx.x, chunk = blockIdx.y;
    __shared__ float kvS[64][64];
    __shared__ float WS[64][65];
    __shared__ float ksS[64];
    __shared__ float bS[64];
    __shared__ float qfmS[8][64];
    __shared__ float tmpS[8][64];
    int tid = threadIdx.x, w = tid >> 5, lane = tid & 31;
    for (int i = tid; i < 4096; i += 256) kvS[i >> 6][i & 63] = g_kvsum[h*D*D + i];
    for (int i = tid; i < 4096; i += 256) WS[i >> 6][i & 63] = W[i];
    if (tid < 64) { ksS[tid] = g_ksum[h*D + tid]; bS[tid] = b[tid]; }
    __syncthreads();
    for (int rr = 0; rr < 16; rr++) {
        int l = chunk*128 + rr*8 + w;
        const float* qr = q + (l*H + h)*D;
        float q0 = qr[lane], q1 = qr[lane + 32];
        float mx = fmaxf(q0, q1);
        #pragma unroll
        for (int o = 16; o > 0; o >>= 1) mx = fmaxf(mx, __shfl_xor_sync(0xffffffffu, mx, o));
        float e0 = __expf(q0 - mx), e1 = __expf(q1 - mx);
        float ssum = e0 + e1;
        #pragma unroll
        for (int o = 16; o > 0; o >>= 1) ssum += __shfl_xor_sync(0xffffffffu, ssum, o);
        float inv = 1.f / ssum;
        float f0 = e0*inv, f1 = e1*inv;
        qfmS[w][lane] = f0; qfmS[w][lane+32] = f1;
        float dn = f0*ksS[lane] + f1*ksS[lane+32];
        #pragma unroll
        for (int o = 16; o > 0; o >>= 1) dn += __shfl_xor_sync(0xffffffffu, dn, o);
        dn += 1e-6f;
        __syncwarp();
        float t0 = 0.f, t1 = 0.f;
        #pragma unroll
        for (int d = 0; d < 64; d++) {
            float qf = qfmS[w][d];
            t0 += qf * kvS[d][lane];
            t1 += qf * kvS[d][lane + 32];
        }
        float invdn = 1.f / dn;
        tmpS[w][lane] = t0*invdn; tmpS[w][lane+32] = t1*invdn;
        __syncwarp();
        float o0 = bS[lane], o1 = bS[lane + 32];
        #pragma unroll
        for (int e = 0; e < 64; e++) {
            float tv = tmpS[w][e];
            o0 += tv * WS[lane][e];
            o1 += tv * WS[lane + 32][e];
        }
        float* op = out + (l*H + h)*D;
        op[lane]      += o0;
        op[lane + 32] += o1;
    }
}

extern "C" void kernel_launch(void* const* d_in, const int* in_sizes, int n_in,
                              void* d_out, int out_size) {
    const float* q = (const float*)d_in[0];
    const float* k = (const float*)d_in[1];
    const float* v = (const float*)d_in[2];
    const float* W = (const float*)d_in[3];
    const float* b = (const float*)d_in[4];
    float* out = (float*)d_out;

    km_kernel<<<H, 256>>>(k);
    convert_kv_kernel<<<dim3(H, NBLK), 128>>>(k, v);
    pooled_kernel<<<dim3(H, M + NBLK), 64>>>(q, k);
    score_kernel<<<dim3(H, M), 256>>>();
    topk_kernel<<<dim3(H, M/8), 256>>>();
    sparse_attn_mma<<<dim3(H, M), 128>>>(q, out);
    kvsum_partial_kernel<<<dim3(H, NCH), 256>>>(k, v);
    reduce_kv_kernel<<<H, 256>>>();
    linear_out_kernel<<<dim3(H, 64), 256>>>(q, W, b, out);
}

// round 8
// speedup vs baseline: 2.0383x; 1.0366x over previous
#include <cuda_runtime.h>
#include <cuda_bf16.h>
#include <math.h>
#include <stdint.h>

#define H 16
#define D 64
#define L 8192
#define M 128
#define NBLK 256
#define T 25
#define NCH 16

#define PADK 72   // K row elems (144 B): ldmatrix rows hit banks 4r..4r+3 -> conflict-free
#define PADV 40   // Vt row elems (80 B): 20r mod 32 distinct -> conflict-free

__device__ float g_km[H*D];
__device__ float g_pq[H*M*D];
__device__ float g_pk[H*NBLK*D];
__device__ float g_score[H*M*NBLK];
__device__ int   g_lut[H*M*T];
__device__ float g_kv_part[NCH*H*D*D];
__device__ float g_ks_part[NCH*H*D];
__device__ float g_kvsum[H*D*D];
__device__ float g_ksum[H*D];
__device__ __nv_bfloat16 g_kch[(size_t)H*NBLK*32*PADK];
__device__ __nv_bfloat16 g_kcl[(size_t)H*NBLK*32*PADK];
__device__ __nv_bfloat16 g_vth[(size_t)H*NBLK*64*PADV];
__device__ __nv_bfloat16 g_vtl[(size_t)H*NBLK*64*PADV];

// ---------------- helpers ----------------
__device__ __forceinline__ uint32_t smem_u32(const void* p) {
    return (uint32_t)__cvta_generic_to_shared(p);
}
__device__ __forceinline__ void cp16(uint32_t saddr, const void* gaddr) {
    asm volatile("cp.async.cg.shared.global [%0], [%1], 16;" :: "r"(saddr), "l"(gaddr));
}
#define CP_COMMIT() asm volatile("cp.async.commit_group;" ::: "memory")
#define CP_WAIT(n)  asm volatile("cp.async.wait_group %0;" :: "n"(n) : "memory")

__device__ __forceinline__ void mma16816(float* c, const uint32_t* a, uint32_t b0, uint32_t b1) {
    asm volatile(
        "mma.sync.aligned.m16n8k16.row.col.f32.bf16.bf16.f32 "
        "{%0,%1,%2,%3}, {%4,%5,%6,%7}, {%8,%9}, {%0,%1,%2,%3};"
        : "+f"(c[0]), "+f"(c[1]), "+f"(c[2]), "+f"(c[3])
        : "r"(a[0]), "r"(a[1]), "r"(a[2]), "r"(a[3]), "r"(b0), "r"(b1));
}
__device__ __forceinline__ void ldmx4(uint32_t& r0, uint32_t& r1, uint32_t& r2, uint32_t& r3,
                                      uint32_t addr) {
    asm volatile("ldmatrix.sync.aligned.m8n8.x4.shared.b16 {%0,%1,%2,%3}, [%4];"
                 : "=r"(r0), "=r"(r1), "=r"(r2), "=r"(r3) : "r"(addr));
}
__device__ __forceinline__ void split_pair(float a, float b, uint32_t& hi, uint32_t& lo) {
    __nv_bfloat16 ha = __float2bfloat16(a);
    __nv_bfloat16 hb = __float2bfloat16(b);
    __nv_bfloat162 hp; hp.x = ha; hp.y = hb;
    __nv_bfloat162 lp; lp.x = __float2bfloat16(a - __bfloat162float(ha));
    lp.y = __float2bfloat16(b - __bfloat162float(hb));
    hi = *(uint32_t*)&hp; lo = *(uint32_t*)&lp;
}

// ================= aux kernels =================
__global__ __launch_bounds__(256) void km_kernel(const float* __restrict__ k) {
    int h = blockIdx.x;
    __shared__ float part[256];
    int tid = threadIdx.x;
    int d = tid & 63, sub = tid >> 6;
    float s = 0.f;
    for (int l = sub; l < L; l += 4) s += k[(l*H + h)*D + d];
    part[tid] = s;
    __syncthreads();
    if (tid < 64) {
        float t = part[tid] + part[tid+64] + part[tid+128] + part[tid+192];
        g_km[h*D + tid] = t * (1.0f/8192.0f);
    }
}

// ===== precompute centered+split K, split+transposed V =====
__global__ __launch_bounds__(128) void convert_kv_kernel(const float* __restrict__ k,
                                                         const float* __restrict__ v) {
    int h = blockIdx.x, n = blockIdx.y;
    int tid = threadIdx.x;
    __shared__ float vS[32][65];
    {
        int vr = tid >> 2, vp = tid & 3;
        const float4* src = (const float4*)(v + ((size_t)(n*32 + vr)*H + h)*D + vp*16);
        #pragma unroll
        for (int i = 0; i < 4; i++) {
            float4 f = src[i];
            vS[vr][vp*16 + 4*i + 0] = f.x;
            vS[vr][vp*16 + 4*i + 1] = f.y;
            vS[vr][vp*16 + 4*i + 2] = f.z;
            vS[vr][vp*16 + 4*i + 3] = f.w;
        }
    }
    {
        int kr = tid >> 2, kp = tid & 3;
        const float4* src = (const float4*)(k + ((size_t)(n*32 + kr)*H + h)*D + kp*16);
        float xs[16];
        #pragma unroll
        for (int i = 0; i < 4; i++) {
            float4 f = src[i];
            xs[4*i+0] = f.x - g_km[h*D + kp*16 + 4*i+0];
            xs[4*i+1] = f.y - g_km[h*D + kp*16 + 4*i+1];
            xs[4*i+2] = f.z - g_km[h*D + kp*16 + 4*i+2];
            xs[4*i+3] = f.w - g_km[h*D + kp*16 + 4*i+3];
        }
        uint32_t hi[8], lo[8];
        #pragma unroll
        for (int j = 0; j < 8; j++) split_pair(xs[2*j], xs[2*j+1], hi[j], lo[j]);
        size_t off = ((size_t)(h*NBLK + n)*32 + kr)*PADK + kp*16;
        *(uint4*)(g_kch + off)     = make_uint4(hi[0],hi[1],hi[2],hi[3]);
        *(uint4*)(g_kch + off + 8) = make_uint4(hi[4],hi[5],hi[6],hi[7]);
        *(uint4*)(g_kcl + off)     = make_uint4(lo[0],lo[1],lo[2],lo[3]);
        *(uint4*)(g_kcl + off + 8) = make_uint4(lo[4],lo[5],lo[6],lo[7]);
    }
    __syncthreads();
    {
        int d = tid & 63, part = tid >> 6;
        uint32_t hi[8], lo[8];
        #pragma unroll
        for (int j = 0; j < 8; j++) {
            float a = vS[part*16 + 2*j][d];
            float b = vS[part*16 + 2*j + 1][d];
            split_pair(a, b, hi[j], lo[j]);
        }
        size_t off = ((size_t)(h*NBLK + n)*64 + d)*PADV + part*16;
        *(uint4*)(g_vth + off)     = make_uint4(hi[0],hi[1],hi[2],hi[3]);
        *(uint4*)(g_vth + off + 8) = make_uint4(hi[4],hi[5],hi[6],hi[7]);
        *(uint4*)(g_vtl + off)     = make_uint4(lo[0],lo[1],lo[2],lo[3]);
        *(uint4*)(g_vtl + off + 8) = make_uint4(lo[4],lo[5],lo[6],lo[7]);
    }
}

__global__ __launch_bounds__(64) void pooled_kernel(const float* __restrict__ q,
                                                    const float* __restrict__ k) {
    int h = blockIdx.x, y = blockIdx.y, d = threadIdx.x;
    if (y < M) {
        float s = 0.f;
        for (int i = 0; i < 64; i++) s += q[((y*64 + i)*H + h)*D + d];
        g_pq[(h*M + y)*D + d] = s * (1.0f/64.0f);
    } else {
        int n = y - M;
        float s = 0.f;
        for (int i = 0; i < 32; i++) s += k[((n*32 + i)*H + h)*D + d];
        g_pk[(h*NBLK + n)*D + d] = s * (1.0f/32.0f) - g_km[h*D + d];
    }
}

// score v2: 16 m per block, pq cached in smem, pk read once per block
__global__ __launch_bounds__(256) void score_kernel() {
    int h = blockIdx.x, mg = blockIdx.y * 16;
    __shared__ float pq[16][64];
    int tid = threadIdx.x;
    for (int i = tid; i < 16*64; i += 256)
        pq[i >> 6][i & 63] = g_pq[(h*M + mg + (i >> 6))*D + (i & 63)];
    __syncthreads();
    const float4* pk = (const float4*)(g_pk + (h*NBLK + tid)*D);
    float acc[16];
    #pragma unroll
    for (int mm = 0; mm < 16; mm++) acc[mm] = 0.f;
    #pragma unroll
    for (int ch = 0; ch < 4; ch++) {
        float4 kv[4];
        #pragma unroll
        for (int i = 0; i < 4; i++) kv[i] = pk[ch*4 + i];
        #pragma unroll
        for (int mm = 0; mm < 16; mm++) {
            float s = 0.f;
            #pragma unroll
            for (int i = 0; i < 4; i++) {
                float4 qv = *(const float4*)(&pq[mm][ch*16 + i*4]);
                s += qv.x*kv[i].x + qv.y*kv[i].y + qv.z*kv[i].z + qv.w*kv[i].w;
            }
            acc[mm] += s;
        }
    }
    #pragma unroll
    for (int mm = 0; mm < 16; mm++)
        g_score[(h*M + mg + mm)*NBLK + tid] = acc[mm];
}

__global__ __launch_bounds__(256) void topk_kernel() {
    int h = blockIdx.x;
    int w = threadIdx.x >> 5, lane = threadIdx.x & 31;
    int m = blockIdx.y*8 + w;
    const float* row = g_score + (h*M + m)*NBLK;
    float v[8];
    #pragma unroll
    for (int j = 0; j < 8; j++) v[j] = row[j*32 + lane];
    int sel[T];
    for (int t = 0; t < T; t++) {
        float bv = -INFINITY; int bi = 1 << 30;
        #pragma unroll
        for (int j = 0; j < 8; j++)
            if (v[j] > bv) { bv = v[j]; bi = j*32 + lane; }
        #pragma unroll
        for (int off = 16; off > 0; off >>= 1) {
            float ov = __shfl_xor_sync(0xffffffffu, bv, off);
            int   oi = __shfl_xor_sync(0xffffffffu, bi, off);
            if (ov > bv || (ov == bv && oi < bi)) { bv = ov; bi = oi; }
        }
        sel[t] = bi;
        if ((bi & 31) == lane) v[bi >> 5] = -INFINITY;
    }
    if (lane == 0) {
        for (int a = 1; a < T; a++) {
            int key = sel[a]; int b = a - 1;
            while (b >= 0 && sel[b] > key) { sel[b+1] = sel[b]; b--; }
            sel[b+1] = key;
        }
        for (int t = 0; t < T; t++) g_lut[(h*M + m)*T + t] = sel[t];
    }
}

// ============ block-sparse attention: cp.async + ldmatrix + mma.sync ============
__global__ __launch_bounds__(128) void sparse_attn_mma(
    const float* __restrict__ q, float* __restrict__ out)
{
    __shared__ __align__(16) __nv_bfloat16 sKh[2][32*PADK];
    __shared__ __align__(16) __nv_bfloat16 sKl[2][32*PADK];
    __shared__ __align__(16) __nv_bfloat16 sVh[2][64*PADV];
    __shared__ __align__(16) __nv_bfloat16 sVl[2][64*PADV];

    const int h = blockIdx.x, m = blockIdx.y;
    const int tid = threadIdx.x;
    const int w = tid >> 5, lane = tid & 31;
    const int g = lane >> 2, tc = lane & 3;
    // ldmatrix per-lane row mapping
    const int lr = lane & 7, quad = lane >> 3;
    const int rowoff = ((quad >> 1) << 3) + lr;   // 0..15
    const int koff = (quad & 1) << 3;             // 0 or 8

    // ---- Q fragments (persistent) ----
    uint32_t aQh[4][4], aQl[4][4];
    {
        int r0 = m*64 + w*16 + g;
        const float* q0 = q + ((size_t)r0*H + h)*D;
        const float* q1 = q + ((size_t)(r0+8)*H + h)*D;
        #pragma unroll
        for (int kt = 0; kt < 4; kt++) {
            int c0 = kt*16 + tc*2;
            float2 f;
            f = *(const float2*)(q0 + c0);     split_pair(f.x, f.y, aQh[kt][0], aQl[kt][0]);
            f = *(const float2*)(q1 + c0);     split_pair(f.x, f.y, aQh[kt][1], aQl[kt][1]);
            f = *(const float2*)(q0 + c0 + 8); split_pair(f.x, f.y, aQh[kt][2], aQl[kt][2]);
            f = *(const float2*)(q1 + c0 + 8); split_pair(f.x, f.y, aQh[kt][3], aQl[kt][3]);
        }
    }

    // cp.async loader maps
    const int krow = tid >> 2, kseg = tid & 3;
    const int vrow = tid >> 1, vseg = tid & 1;
    const uint32_t ksm = (uint32_t)(krow*PADK + kseg*16)*2;
    const uint32_t vsm = (uint32_t)(vrow*PADV + vseg*16)*2;
    const size_t   kgo = (size_t)krow*PADK + kseg*16;
    const size_t   vgo = (size_t)vrow*PADV + vseg*16;
    const int* lut = g_lut + (h*M + m)*T;

    #define LOAD_STAGE(n_, buf_) do { \
        size_t kb = ((size_t)(h*NBLK + (n_)))*32*PADK + kgo; \
        size_t vb = ((size_t)(h*NBLK + (n_)))*64*PADV + vgo; \
        uint32_t skh = smem_u32(&sKh[buf_][0]) + ksm; \
        uint32_t skl = smem_u32(&sKl[buf_][0]) + ksm; \
        uint32_t svh = smem_u32(&sVh[buf_][0]) + vsm; \
        uint32_t svl = smem_u32(&sVl[buf_][0]) + vsm; \
        cp16(skh,      g_kch + kb); \
        cp16(skh + 16, g_kch + kb + 8); \
        cp16(skl,      g_kcl + kb); \
        cp16(skl + 16, g_kcl + kb + 8); \
        cp16(svh,      g_vth + vb); \
        cp16(svh + 16, g_vth + vb + 8); \
        cp16(svl,      g_vtl + vb); \
        cp16(svl + 16, g_vtl + vb + 8); \
    } while (0)

    float o[8][4];
    #pragma unroll
    for (int a = 0; a < 8; a++)
        #pragma unroll
        for (int j = 0; j < 4; j++) o[a][j] = 0.f;
    float lrow0 = 0.f, lrow1 = 0.f;

    LOAD_STAGE(lut[0], 0);
    CP_COMMIT();

    for (int t = 0; t < T; t++) {
        int buf = t & 1;
        if (t + 1 < T) {
            LOAD_STAGE(lut[t+1], (t+1) & 1);
            CP_COMMIT();
            CP_WAIT(1);
        } else {
            CP_WAIT(0);
        }
        __syncthreads();

        const uint32_t aKh = smem_u32(&sKh[buf][0]) + (uint32_t)(rowoff*PADK + koff)*2;
        const uint32_t aKl = smem_u32(&sKl[buf][0]) + (uint32_t)(rowoff*PADK + koff)*2;
        const uint32_t aVh = smem_u32(&sVh[buf][0]) + (uint32_t)(rowoff*PADV + koff)*2;
        const uint32_t aVl = smem_u32(&sVl[buf][0]) + (uint32_t)(rowoff*PADV + koff)*2;

        // ---- QK: S[16q x 32k], 3-pass split, ldmatrix B ----
        float c[4][4];
        #pragma unroll
        for (int nt = 0; nt < 4; nt++)
            #pragma unroll
            for (int j = 0; j < 4; j++) c[nt][j] = 0.f;
        #pragma unroll
        for (int ntp = 0; ntp < 2; ntp++) {
            #pragma unroll
            for (int kt = 0; kt < 4; kt++) {
                uint32_t off = (uint32_t)(ntp*16*PADK + kt*16)*2;
                uint32_t h0,h1,h2,h3, l0,l1,l2,l3;
                ldmx4(h0,h1,h2,h3, aKh + off);
                ldmx4(l0,l1,l2,l3, aKl + off);
                mma16816(c[2*ntp],   aQh[kt], h0, h1);
                mma16816(c[2*ntp],   aQl[kt], h0, h1);
                mma16816(c[2*ntp],   aQh[kt], l0, l1);
                mma16816(c[2*ntp+1], aQh[kt], h2, h3);
                mma16816(c[2*ntp+1], aQl[kt], h2, h3);
                mma16816(c[2*ntp+1], aQh[kt], l2, l3);
            }
        }
        // ---- exp + row sums ----
        float pr[4][4];
        float rs0 = 0.f, rs1 = 0.f;
        #pragma unroll
        for (int nt = 0; nt < 4; nt++) {
            #pragma unroll
            for (int j = 0; j < 4; j++) pr[nt][j] = __expf(c[nt][j] * 0.125f);
            rs0 += pr[nt][0] + pr[nt][1];
            rs1 += pr[nt][2] + pr[nt][3];
        }
        rs0 += __shfl_xor_sync(0xffffffffu, rs0, 1);
        rs0 += __shfl_xor_sync(0xffffffffu, rs0, 2);
        rs1 += __shfl_xor_sync(0xffffffffu, rs1, 1);
        rs1 += __shfl_xor_sync(0xffffffffu, rs1, 2);
        lrow0 += rs0; lrow1 += rs1;

        // ---- P fragments ----
        uint32_t aPh[2][4], aPl[2][4];
        #pragma unroll
        for (int kp2 = 0; kp2 < 2; kp2++) {
            split_pair(pr[2*kp2][0],   pr[2*kp2][1],   aPh[kp2][0], aPl[kp2][0]);
            split_pair(pr[2*kp2][2],   pr[2*kp2][3],   aPh[kp2][1], aPl[kp2][1]);
            split_pair(pr[2*kp2+1][0], pr[2*kp2+1][1], aPh[kp2][2], aPl[kp2][2]);
            split_pair(pr[2*kp2+1][2], pr[2*kp2+1][3], aPh[kp2][3], aPl[kp2][3]);
        }
        // ---- PV: O += P x V, ldmatrix B ----
        #pragma unroll
        for (int nvp = 0; nvp < 4; nvp++) {
            #pragma unroll
            for (int kp2 = 0; kp2 < 2; kp2++) {
                uint32_t off = (uint32_t)(nvp*16*PADV + kp2*16)*2;
                uint32_t h0,h1,h2,h3, l0,l1,l2,l3;
                ldmx4(h0,h1,h2,h3, aVh + off);
                ldmx4(l0,l1,l2,l3, aVl + off);
                mma16816(o[2*nvp],   aPh[kp2], h0, h1);
                mma16816(o[2*nvp],   aPl[kp2], h0, h1);
                mma16816(o[2*nvp],   aPh[kp2], l0, l1);
                mma16816(o[2*nvp+1], aPh[kp2], h2, h3);
                mma16816(o[2*nvp+1], aPl[kp2], h2, h3);
                mma16816(o[2*nvp+1], aPh[kp2], l2, l3);
            }
        }
        __syncthreads();
    }

    // ---- epilogue ----
    float inv0 = 1.f / lrow0;
    float inv1 = 1.f / lrow1;
    int r0 = m*64 + w*16 + g;
    float* out0 = out + ((size_t)r0*H + h)*D;
    float* out1 = out + ((size_t)(r0+8)*H + h)*D;
    #pragma unroll
    for (int nv = 0; nv < 8; nv++) {
        int cc = nv*8 + tc*2;
        *(float2*)(out0 + cc) = make_float2(o[nv][0]*inv0, o[nv][1]*inv0);
        *(float2*)(out1 + cc) = make_float2(o[nv][2]*inv1, o[nv][3]*inv1);
    }
    #undef LOAD_STAGE
}

// ====== kvsum partials (no max-sub: k ~ N(0,1), exp safe; softmax shift-invariant) ======
__global__ __launch_bounds__(256) void kvsum_partial_kernel(const float* __restrict__ k,
                                                            const float* __restrict__ v) {
    int h = blockIdx.x, c = blockIdx.y;
    __shared__ float kfS[8][64];
    __shared__ float vS[8][64];
    int tid = threadIdx.x, w = tid >> 5, lane = tid & 31;
    int e = tid & 63, g = tid >> 6;
    int d0 = g * 16;
    float acc[16];
    #pragma unroll
    for (int j = 0; j < 16; j++) acc[j] = 0.f;
    float ks_acc = 0.f;
    for (int sIt = 0; sIt < 64; sIt++) {
        int l = c*512 + sIt*8 + w;
        __syncthreads();
        const float* kr = k + (l*H + h)*D;
        const float* vr = v + (l*H + h)*D;
        float e0 = __expf(kr[lane]), e1 = __expf(kr[lane + 32]);
        float sm = e0 + e1;
        #pragma unroll
        for (int o = 16; o > 0; o >>= 1) sm += __shfl_xor_sync(0xffffffffu, sm, o);
        float inv = 1.f / sm;
        kfS[w][lane] = e0*inv; kfS[w][lane+32] = e1*inv;
        vS[w][lane] = vr[lane]; vS[w][lane+32] = vr[lane+32];
        __syncthreads();
        #pragma unroll
        for (int rr = 0; rr < 8; rr++) {
            float ve = vS[rr][e];
            #pragma unroll
            for (int j = 0; j < 16; j++) acc[j] += kfS[rr][d0 + j] * ve;
        }
        if (g == 0) {
            #pragma unroll
            for (int rr = 0; rr < 8; rr++) ks_acc += kfS[rr][e];
        }
    }
    float* dst = g_kv_part + (c*H + h)*D*D;
    #pragma unroll
    for (int j = 0; j < 16; j++) dst[(d0 + j)*D + e] = acc[j];
    if (g == 0) g_ks_part[(c*H + h)*D + e] = ks_acc;
}
__global__ __launch_bounds__(256) void reduce_kv_kernel() {
    int h = blockIdx.x;
    for (int i = threadIdx.x; i < D*D; i += 256) {
        float s = 0.f;
        for (int c = 0; c < NCH; c++) s += g_kv_part[(c*H + h)*D*D + i];
        g_kvsum[h*D*D + i] = s;
    }
    for (int i = threadIdx.x; i < D; i += 256) {
        float s = 0.f;
        for (int c = 0; c < NCH; c++) s += g_ks_part[(c*H + h)*D + i];
        g_ksum[h*D + i] = s;
    }
}
__global__ __launch_bounds__(256) void linear_out_kernel(const float* __restrict__ q,
                                                         const float* __restrict__ W,
                                                         const float* __restrict__ b,
                                                         float* __restrict__ out) {
    int h = blockIdx.x, chunk = blockIdx.y;
    __shared__ float kvS[64][64];
    __shared__ float WS[64][65];
    __shared__ float ksS[64];
    __shared__ float bS[64];
    __shared__ float qfmS[8][64];
    __shared__ float tmpS[8][64];
    int tid = threadIdx.x, w = tid >> 5, lane = tid & 31;
    for (int i = tid; i < 4096; i += 256) kvS[i >> 6][i & 63] = g_kvsum[h*D*D + i];
    for (int i = tid; i < 4096; i += 256) WS[i >> 6][i & 63] = W[i];
    if (tid < 64) { ksS[tid] = g_ksum[h*D + tid]; bS[tid] = b[tid]; }
    __syncthreads();
    for (int rr = 0; rr < 16; rr++) {
        int l = chunk*128 + rr*8 + w;
        const float* qr = q + (l*H + h)*D;
        float q0 = qr[lane], q1 = qr[lane + 32];
        float mx = fmaxf(q0, q1);
        #pragma unroll
        for (int o = 16; o > 0; o >>= 1) mx = fmaxf(mx, __shfl_xor_sync(0xffffffffu, mx, o));
        float e0 = __expf(q0 - mx), e1 = __expf(q1 - mx);
        float ssum = e0 + e1;
        #pragma unroll
        for (int o = 16; o > 0; o >>= 1) ssum += __shfl_xor_sync(0xffffffffu, ssum, o);
        float inv = 1.f / ssum;
        float f0 = e0*inv, f1 = e1*inv;
        qfmS[w][lane] = f0; qfmS[w][lane+32] = f1;
        float dn = f0*ksS[lane] + f1*ksS[lane+32];
        #pragma unroll
        for (int o = 16; o > 0; o >>= 1) dn += __shfl_xor_sync(0xffffffffu, dn, o);
        dn += 1e-6f;
        __syncwarp();
        float t0 = 0.f, t1 = 0.f;
        #pragma unroll
        for (int d = 0; d < 64; d++) {
            float qf = qfmS[w][d];
            t0 += qf * kvS[d][lane];
            t1 += qf * kvS[d][lane + 32];
        }
        float invdn = 1.f / dn;
        tmpS[w][lane] = t0*invdn; tmpS[w][lane+32] = t1*invdn;
        __syncwarp();
        float o0 = bS[lane], o1 = bS[lane + 32];
        #pragma unroll
        for (int e = 0; e < 64; e++) {
            float tv = tmpS[w][e];
            o0 += tv * WS[lane][e];
            o1 += tv * WS[lane + 32][e];
        }
        float* op = out + (l*H + h)*D;
        op[lane]      += o0;
        op[lane + 32] += o1;
    }
}

extern "C" void kernel_launch(void* const* d_in, const int* in_sizes, int n_in,
                              void* d_out, int out_size) {
    const float* q = (const float*)d_in[0];
    const float* k = (const float*)d_in[1];
    const float* v = (const float*)d_in[2];
    const float* W = (const float*)d_in[3];
    const float* b = (const float*)d_in[4];
    float* out = (float*)d_out;

    km_kernel<<<H, 256>>>(k);
    convert_kv_kernel<<<dim3(H, NBLK), 128>>>(k, v);
    pooled_kernel<<<dim3(H, M + NBLK), 64>>>(q, k);
    score_kernel<<<dim3(H, M/16), 256>>>();
    topk_kernel<<<dim3(H, M/8), 256>>>();
    sparse_attn_mma<<<dim3(H, M), 128>>>(q, out);
    kvsum_partial_kernel<<<dim3(H, NCH), 256>>>(k, v);
    reduce_kv_kernel<<<H, 256>>>();
    linear_out_kernel<<<dim3(H, 64), 256>>>(q, W, b, out);
}

// round 9
// speedup vs baseline: 2.1900x; 1.0744x over previous
#include <cuda_runtime.h>
#include <cuda_bf16.h>
#include <math.h>
#include <stdint.h>

#define H 16
#define D 64
#define L 8192
#define M 128
#define NBLK 256
#define T 25
#define NCH 16

#define PADK 72   // K smem row elems (144 B): ldmatrix rows conflict-free
#define PADV 40   // Vt smem row elems (80 B): conflict-free

__device__ float g_km[H*D];
__device__ float g_pq[H*M*D];
__device__ float g_pk[H*NBLK*D];
__device__ int   g_lut[H*M*T];
__device__ float g_kv_part[NCH*H*D*D];
__device__ float g_ks_part[NCH*H*D];
__device__ float g_kvsum[H*D*D];
__device__ float g_ksum[H*D];
// dense gmem layout: K block = 32x64, Vt block = 64x32 (pads only in smem)
__device__ __nv_bfloat16 g_kch[(size_t)H*NBLK*32*64];
__device__ __nv_bfloat16 g_kcl[(size_t)H*NBLK*32*64];
__device__ __nv_bfloat16 g_vth[(size_t)H*NBLK*64*32];
__device__ __nv_bfloat16 g_vtl[(size_t)H*NBLK*64*32];

// ---------------- helpers ----------------
__device__ __forceinline__ uint32_t smem_u32(const void* p) {
    return (uint32_t)__cvta_generic_to_shared(p);
}
__device__ __forceinline__ void cp16(uint32_t saddr, const void* gaddr) {
    asm volatile("cp.async.cg.shared.global [%0], [%1], 16;" :: "r"(saddr), "l"(gaddr));
}
#define CP_COMMIT() asm volatile("cp.async.commit_group;" ::: "memory")
#define CP_WAIT(n)  asm volatile("cp.async.wait_group %0;" :: "n"(n) : "memory")

__device__ __forceinline__ void mma16816(float* c, const uint32_t* a, uint32_t b0, uint32_t b1) {
    asm volatile(
        "mma.sync.aligned.m16n8k16.row.col.f32.bf16.bf16.f32 "
        "{%0,%1,%2,%3}, {%4,%5,%6,%7}, {%8,%9}, {%0,%1,%2,%3};"
        : "+f"(c[0]), "+f"(c[1]), "+f"(c[2]), "+f"(c[3])
        : "r"(a[0]), "r"(a[1]), "r"(a[2]), "r"(a[3]), "r"(b0), "r"(b1));
}
__device__ __forceinline__ void ldmx4(uint32_t& r0, uint32_t& r1, uint32_t& r2, uint32_t& r3,
                                      uint32_t addr) {
    asm volatile("ldmatrix.sync.aligned.m8n8.x4.shared.b16 {%0,%1,%2,%3}, [%4];"
                 : "=r"(r0), "=r"(r1), "=r"(r2), "=r"(r3) : "r"(addr));
}
__device__ __forceinline__ void split_pair(float a, float b, uint32_t& hi, uint32_t& lo) {
    __nv_bfloat16 ha = __float2bfloat16(a);
    __nv_bfloat16 hb = __float2bfloat16(b);
    __nv_bfloat162 hp; hp.x = ha; hp.y = hb;
    __nv_bfloat162 lp; lp.x = __float2bfloat16(a - __bfloat162float(ha));
    lp.y = __float2bfloat16(b - __bfloat162float(hb));
    hi = *(uint32_t*)&hp; lo = *(uint32_t*)&lp;
}

// ===== prep: km (y=0), pooled_q (y=1..M), pooled_k uncentered (y=M+1..M+NBLK) =====
__global__ __launch_bounds__(256) void prep_kernel(const float* __restrict__ q,
                                                   const float* __restrict__ k) {
    int h = blockIdx.x, y = blockIdx.y;
    int tid = threadIdx.x;
    __shared__ float part[256];
    int d = tid & 63, sub = tid >> 6;
    if (y == 0) {
        float s = 0.f;
        for (int l = sub; l < L; l += 4) s += k[(l*H + h)*D + d];
        part[tid] = s;
        __syncthreads();
        if (tid < 64)
            g_km[h*D + tid] = (part[tid] + part[tid+64] + part[tid+128] + part[tid+192]) * (1.0f/8192.0f);
    } else if (y <= M) {
        int m = y - 1;
        float s = 0.f;
        for (int i = sub; i < 64; i += 4) s += q[((m*64 + i)*H + h)*D + d];
        part[tid] = s;
        __syncthreads();
        if (tid < 64)
            g_pq[(h*M + m)*D + tid] = (part[tid] + part[tid+64] + part[tid+128] + part[tid+192]) * (1.0f/64.0f);
    } else {
        int n = y - M - 1;
        float s = 0.f;
        for (int i = sub; i < 32; i += 4) s += k[((n*32 + i)*H + h)*D + d];
        part[tid] = s;
        __syncthreads();
        if (tid < 64)
            g_pk[(h*NBLK + n)*D + tid] = (part[tid] + part[tid+64] + part[tid+128] + part[tid+192]) * (1.0f/32.0f);
    }
}

// ===== fused score + topk: 16 m per block =====
__global__ __launch_bounds__(256) void scoretopk_kernel() {
    int h = blockIdx.x, mg = blockIdx.y * 16;
    __shared__ float pq[16][64];
    __shared__ float kmS[64];
    __shared__ float corr[16];
    __shared__ float sc[16][NBLK];
    int tid = threadIdx.x;
    for (int i = tid; i < 16*64; i += 256)
        pq[i >> 6][i & 63] = g_pq[(h*M + mg + (i >> 6))*D + (i & 63)];
    if (tid < 64) kmS[tid] = g_km[h*D + tid];
    __syncthreads();
    if (tid < 16) {
        float s = 0.f;
        #pragma unroll
        for (int d = 0; d < 64; d++) s += pq[tid][d] * kmS[d];
        corr[tid] = s;
    }
    __syncthreads();
    // scores: thread = n
    const float4* pk = (const float4*)(g_pk + (h*NBLK + tid)*D);
    float acc[16];
    #pragma unroll
    for (int mm = 0; mm < 16; mm++) acc[mm] = 0.f;
    #pragma unroll
    for (int ch = 0; ch < 4; ch++) {
        float4 kv[4];
        #pragma unroll
        for (int i = 0; i < 4; i++) kv[i] = pk[ch*4 + i];
        #pragma unroll
        for (int mm = 0; mm < 16; mm++) {
            float s = 0.f;
            #pragma unroll
            for (int i = 0; i < 4; i++) {
                float4 qv = *(const float4*)(&pq[mm][ch*16 + i*4]);
                s += qv.x*kv[i].x + qv.y*kv[i].y + qv.z*kv[i].z + qv.w*kv[i].w;
            }
            acc[mm] += s;
        }
    }
    #pragma unroll
    for (int mm = 0; mm < 16; mm++) sc[mm][tid] = acc[mm] - corr[mm];
    __syncthreads();
    // topk: 8 warps, 2 m each
    int w = tid >> 5, lane = tid & 31;
    for (int s2 = 0; s2 < 2; s2++) {
        int mloc = w*2 + s2;
        float v[8];
        #pragma unroll
        for (int j = 0; j < 8; j++) v[j] = sc[mloc][j*32 + lane];
        int sel[T];
        for (int t = 0; t < T; t++) {
            float bv = -INFINITY; int bi = 1 << 30;
            #pragma unroll
            for (int j = 0; j < 8; j++)
                if (v[j] > bv) { bv = v[j]; bi = j*32 + lane; }
            #pragma unroll
            for (int off = 16; off > 0; off >>= 1) {
                float ov = __shfl_xor_sync(0xffffffffu, bv, off);
                int   oi = __shfl_xor_sync(0xffffffffu, bi, off);
                if (ov > bv || (ov == bv && oi < bi)) { bv = ov; bi = oi; }
            }
            sel[t] = bi;
            if ((bi & 31) == lane) v[bi >> 5] = -INFINITY;
        }
        if (lane == 0) {
            for (int a = 1; a < T; a++) {
                int key = sel[a]; int b = a - 1;
                while (b >= 0 && sel[b] > key) { sel[b+1] = sel[b]; b--; }
                sel[b+1] = key;
            }
            for (int t = 0; t < T; t++) g_lut[(h*M + mg + mloc)*T + t] = sel[t];
        }
    }
}

// ===== precompute centered+split K (dense 32x64), split+transposed V (dense 64x32) =====
__global__ __launch_bounds__(128) void convert_kv_kernel(const float* __restrict__ k,
                                                         const float* __restrict__ v) {
    int h = blockIdx.x, n = blockIdx.y;
    int tid = threadIdx.x;
    __shared__ float vS[32][65];
    {
        int vr = tid >> 2, vp = tid & 3;
        const float4* src = (const float4*)(v + ((size_t)(n*32 + vr)*H + h)*D + vp*16);
        #pragma unroll
        for (int i = 0; i < 4; i++) {
            float4 f = src[i];
            vS[vr][vp*16 + 4*i + 0] = f.x;
            vS[vr][vp*16 + 4*i + 1] = f.y;
            vS[vr][vp*16 + 4*i + 2] = f.z;
            vS[vr][vp*16 + 4*i + 3] = f.w;
        }
    }
    {
        int kr = tid >> 2, kp = tid & 3;
        const float4* src = (const float4*)(k + ((size_t)(n*32 + kr)*H + h)*D + kp*16);
        float xs[16];
        #pragma unroll
        for (int i = 0; i < 4; i++) {
            float4 f = src[i];
            xs[4*i+0] = f.x - g_km[h*D + kp*16 + 4*i+0];
            xs[4*i+1] = f.y - g_km[h*D + kp*16 + 4*i+1];
            xs[4*i+2] = f.z - g_km[h*D + kp*16 + 4*i+2];
            xs[4*i+3] = f.w - g_km[h*D + kp*16 + 4*i+3];
        }
        uint32_t hi[8], lo[8];
        #pragma unroll
        for (int j = 0; j < 8; j++) split_pair(xs[2*j], xs[2*j+1], hi[j], lo[j]);
        size_t off = ((size_t)(h*NBLK + n)*32 + kr)*64 + kp*16;
        *(uint4*)(g_kch + off)     = make_uint4(hi[0],hi[1],hi[2],hi[3]);
        *(uint4*)(g_kch + off + 8) = make_uint4(hi[4],hi[5],hi[6],hi[7]);
        *(uint4*)(g_kcl + off)     = make_uint4(lo[0],lo[1],lo[2],lo[3]);
        *(uint4*)(g_kcl + off + 8) = make_uint4(lo[4],lo[5],lo[6],lo[7]);
    }
    __syncthreads();
    {
        int d = tid & 63, part = tid >> 6;
        uint32_t hi[8], lo[8];
        #pragma unroll
        for (int j = 0; j < 8; j++) {
            float a = vS[part*16 + 2*j][d];
            float b = vS[part*16 + 2*j + 1][d];
            split_pair(a, b, hi[j], lo[j]);
        }
        size_t off = ((size_t)(h*NBLK + n)*64 + d)*32 + part*16;
        *(uint4*)(g_vth + off)     = make_uint4(hi[0],hi[1],hi[2],hi[3]);
        *(uint4*)(g_vth + off + 8) = make_uint4(hi[4],hi[5],hi[6],hi[7]);
        *(uint4*)(g_vtl + off)     = make_uint4(lo[0],lo[1],lo[2],lo[3]);
        *(uint4*)(g_vtl + off + 8) = make_uint4(lo[4],lo[5],lo[6],lo[7]);
    }
}

// ============ block-sparse attention: cp.async + ldmatrix + mma.sync ============
__global__ __launch_bounds__(128) void sparse_attn_mma(
    const float* __restrict__ q, float* __restrict__ out)
{
    __shared__ __align__(16) __nv_bfloat16 sKh[2][32*PADK];
    __shared__ __align__(16) __nv_bfloat16 sKl[2][32*PADK];
    __shared__ __align__(16) __nv_bfloat16 sVh[2][64*PADV];
    __shared__ __align__(16) __nv_bfloat16 sVl[2][64*PADV];

    const int h = blockIdx.x, m = blockIdx.y;
    const int tid = threadIdx.x;
    const int w = tid >> 5, lane = tid & 31;
    const int g = lane >> 2, tc = lane & 3;
    const int lr = lane & 7, quad = lane >> 3;
    const int rowoff = ((quad >> 1) << 3) + lr;
    const int koff = (quad & 1) << 3;

    // ---- Q fragments (persistent) ----
    uint32_t aQh[4][4], aQl[4][4];
    {
        int r0 = m*64 + w*16 + g;
        const float* q0 = q + ((size_t)r0*H + h)*D;
        const float* q1 = q + ((size_t)(r0+8)*H + h)*D;
        #pragma unroll
        for (int kt = 0; kt < 4; kt++) {
            int c0 = kt*16 + tc*2;
            float2 f;
            f = *(const float2*)(q0 + c0);     split_pair(f.x, f.y, aQh[kt][0], aQl[kt][0]);
            f = *(const float2*)(q1 + c0);     split_pair(f.x, f.y, aQh[kt][1], aQl[kt][1]);
            f = *(const float2*)(q0 + c0 + 8); split_pair(f.x, f.y, aQh[kt][2], aQl[kt][2]);
            f = *(const float2*)(q1 + c0 + 8); split_pair(f.x, f.y, aQh[kt][3], aQl[kt][3]);
        }
    }

    // cp.async loader maps (dense gmem, padded smem)
    const int krow = tid >> 2, kseg = tid & 3;
    const int vrow = tid >> 1, vseg = tid & 1;
    const uint32_t ksm = (uint32_t)(krow*PADK + kseg*16)*2;
    const uint32_t vsm = (uint32_t)(vrow*PADV + vseg*16)*2;
    const size_t   kgo = (size_t)krow*64 + kseg*16;
    const size_t   vgo = (size_t)vrow*32 + vseg*16;
    const int* lut = g_lut + (h*M + m)*T;

    #define LOAD_STAGE(n_, buf_) do { \
        size_t kb = ((size_t)(h*NBLK + (n_)))*2048 + kgo; \
        size_t vb = ((size_t)(h*NBLK + (n_)))*2048 + vgo; \
        uint32_t skh = smem_u32(&sKh[buf_][0]) + ksm; \
        uint32_t skl = smem_u32(&sKl[buf_][0]) + ksm; \
        uint32_t svh = smem_u32(&sVh[buf_][0]) + vsm; \
        uint32_t svl = smem_u32(&sVl[buf_][0]) + vsm; \
        cp16(skh,      g_kch + kb); \
        cp16(skh + 16, g_kch + kb + 8); \
        cp16(skl,      g_kcl + kb); \
        cp16(skl + 16, g_kcl + kb + 8); \
        cp16(svh,      g_vth + vb); \
        cp16(svh + 16, g_vth + vb + 8); \
        cp16(svl,      g_vtl + vb); \
        cp16(svl + 16, g_vtl + vb + 8); \
    } while (0)

    float o[8][4];
    #pragma unroll
    for (int a = 0; a < 8; a++)
        #pragma unroll
        for (int j = 0; j < 4; j++) o[a][j] = 0.f;
    float lrow0 = 0.f, lrow1 = 0.f;

    LOAD_STAGE(lut[0], 0);
    CP_COMMIT();

    for (int t = 0; t < T; t++) {
        int buf = t & 1;
        if (t + 1 < T) {
            LOAD_STAGE(lut[t+1], (t+1) & 1);
            CP_COMMIT();
            CP_WAIT(1);
        } else {
            CP_WAIT(0);
        }
        __syncthreads();

        const uint32_t aKh = smem_u32(&sKh[buf][0]) + (uint32_t)(rowoff*PADK + koff)*2;
        const uint32_t aKl = smem_u32(&sKl[buf][0]) + (uint32_t)(rowoff*PADK + koff)*2;
        const uint32_t aVh = smem_u32(&sVh[buf][0]) + (uint32_t)(rowoff*PADV + koff)*2;
        const uint32_t aVl = smem_u32(&sVl[buf][0]) + (uint32_t)(rowoff*PADV + koff)*2;

        // ---- QK: S[16q x 32k], 3-pass split ----
        float c[4][4];
        #pragma unroll
        for (int nt = 0; nt < 4; nt++)
            #pragma unroll
            for (int j = 0; j < 4; j++) c[nt][j] = 0.f;
        #pragma unroll
        for (int ntp = 0; ntp < 2; ntp++) {
            #pragma unroll
            for (int kt = 0; kt < 4; kt++) {
                uint32_t off = (uint32_t)(ntp*16*PADK + kt*16)*2;
                uint32_t h0,h1,h2,h3, l0,l1,l2,l3;
                ldmx4(h0,h1,h2,h3, aKh + off);
                ldmx4(l0,l1,l2,l3, aKl + off);
                mma16816(c[2*ntp],   aQh[kt], h0, h1);
                mma16816(c[2*ntp],   aQl[kt], h0, h1);
                mma16816(c[2*ntp],   aQh[kt], l0, l1);
                mma16816(c[2*ntp+1], aQh[kt], h2, h3);
                mma16816(c[2*ntp+1], aQl[kt], h2, h3);
                mma16816(c[2*ntp+1], aQh[kt], l2, l3);
            }
        }
        // ---- exp + row sums ----
        float pr[4][4];
        float rs0 = 0.f, rs1 = 0.f;
        #pragma unroll
        for (int nt = 0; nt < 4; nt++) {
            #pragma unroll
            for (int j = 0; j < 4; j++) pr[nt][j] = __expf(c[nt][j] * 0.125f);
            rs0 += pr[nt][0] + pr[nt][1];
            rs1 += pr[nt][2] + pr[nt][3];
        }
        rs0 += __shfl_xor_sync(0xffffffffu, rs0, 1);
        rs0 += __shfl_xor_sync(0xffffffffu, rs0, 2);
        rs1 += __shfl_xor_sync(0xffffffffu, rs1, 1);
        rs1 += __shfl_xor_sync(0xffffffffu, rs1, 2);
        lrow0 += rs0; lrow1 += rs1;

        // ---- P fragments ----
        uint32_t aPh[2][4], aPl[2][4];
        #pragma unroll
        for (int kp2 = 0; kp2 < 2; kp2++) {
            split_pair(pr[2*kp2][0],   pr[2*kp2][1],   aPh[kp2][0], aPl[kp2][0]);
            split_pair(pr[2*kp2][2],   pr[2*kp2][3],   aPh[kp2][1], aPl[kp2][1]);
            split_pair(pr[2*kp2+1][0], pr[2*kp2+1][1], aPh[kp2][2], aPl[kp2][2]);
            split_pair(pr[2*kp2+1][2], pr[2*kp2+1][3], aPh[kp2][3], aPl[kp2][3]);
        }
        // ---- PV ----
        #pragma unroll
        for (int nvp = 0; nvp < 4; nvp++) {
            #pragma unroll
            for (int kp2 = 0; kp2 < 2; kp2++) {
                uint32_t off = (uint32_t)(nvp*16*PADV + kp2*16)*2;
                uint32_t h0,h1,h2,h3, l0,l1,l2,l3;
                ldmx4(h0,h1,h2,h3, aVh + off);
                ldmx4(l0,l1,l2,l3, aVl + off);
                mma16816(o[2*nvp],   aPh[kp2], h0, h1);
                mma16816(o[2*nvp],   aPl[kp2], h0, h1);
                mma16816(o[2*nvp],   aPh[kp2], l0, l1);
                mma16816(o[2*nvp+1], aPh[kp2], h2, h3);
                mma16816(o[2*nvp+1], aPl[kp2], h2, h3);
                mma16816(o[2*nvp+1], aPh[kp2], l2, l3);
            }
        }
        __syncthreads();
    }

    // ---- epilogue ----
    float inv0 = 1.f / lrow0;
    float inv1 = 1.f / lrow1;
    int r0 = m*64 + w*16 + g;
    float* out0 = out + ((size_t)r0*H + h)*D;
    float* out1 = out + ((size_t)(r0+8)*H + h)*D;
    #pragma unroll
    for (int nv = 0; nv < 8; nv++) {
        int cc = nv*8 + tc*2;
        *(float2*)(out0 + cc) = make_float2(o[nv][0]*inv0, o[nv][1]*inv0);
        *(float2*)(out1 + cc) = make_float2(o[nv][2]*inv1, o[nv][3]*inv1);
    }
    #undef LOAD_STAGE
}

// ====== kvsum partials ======
__global__ __launch_bounds__(256) void kvsum_partial_kernel(const float* __restrict__ k,
                                                            const float* __restrict__ v) {
    int h = blockIdx.x, c = blockIdx.y;
    __shared__ float kfS[8][64];
    __shared__ float vS[8][64];
    int tid = threadIdx.x, w = tid >> 5, lane = tid & 31;
    int e = tid & 63, g = tid >> 6;
    int d0 = g * 16;
    float acc[16];
    #pragma unroll
    for (int j = 0; j < 16; j++) acc[j] = 0.f;
    float ks_acc = 0.f;
    for (int sIt = 0; sIt < 64; sIt++) {
        int l = c*512 + sIt*8 + w;
        __syncthreads();
        const float* kr = k + (l*H + h)*D;
        const float* vr = v + (l*H + h)*D;
        float e0 = __expf(kr[lane]), e1 = __expf(kr[lane + 32]);
        float sm = e0 + e1;
        #pragma unroll
        for (int o = 16; o > 0; o >>= 1) sm += __shfl_xor_sync(0xffffffffu, sm, o);
        float inv = 1.f / sm;
        kfS[w][lane] = e0*inv; kfS[w][lane+32] = e1*inv;
        vS[w][lane] = vr[lane]; vS[w][lane+32] = vr[lane+32];
        __syncthreads();
        #pragma unroll
        for (int rr = 0; rr < 8; rr++) {
            float ve = vS[rr][e];
            #pragma unroll
            for (int j = 0; j < 16; j++) acc[j] += kfS[rr][d0 + j] * ve;
        }
        if (g == 0) {
            #pragma unroll
            for (int rr = 0; rr < 8; rr++) ks_acc += kfS[rr][e];
        }
    }
    float* dst = g_kv_part + (c*H + h)*D*D;
    #pragma unroll
    for (int j = 0; j < 16; j++) dst[(d0 + j)*D + e] = acc[j];
    if (g == 0) g_ks_part[(c*H + h)*D + e] = ks_acc;
}
__global__ __launch_bounds__(256) void reduce_kv_kernel() {
    int h = blockIdx.x;
    for (int i = threadIdx.x; i < D*D; i += 256) {
        float s = 0.f;
        for (int c = 0; c < NCH; c++) s += g_kv_part[(c*H + h)*D*D + i];
        g_kvsum[h*D*D + i] = s;
    }
    for (int i = threadIdx.x; i < D; i += 256) {
        float s = 0.f;
        for (int c = 0; c < NCH; c++) s += g_ks_part[(c*H + h)*D + i];
        g_ksum[h*D + i] = s;
    }
}
__global__ __launch_bounds__(256) void linear_out_kernel(const float* __restrict__ q,
                                                         const float* __restrict__ W,
                                                         const float* __restrict__ b,
                                                         float* __restrict__ out) {
    int h = blockIdx.x, chunk = blockIdx.y;
    __shared__ float kvS[64][64];
    __shared__ float WS[64][65];
    __shared__ float ksS[64];
    __shared__ float bS[64];
    __shared__ float qfmS[8][64];
    __shared__ float tmpS[8][64];
    int tid = threadIdx.x, w = tid >> 5, lane = tid & 31;
    for (int i = tid; i < 4096; i += 256) kvS[i >> 6][i & 63] = g_kvsum[h*D*D + i];
    for (int i = tid; i < 4096; i += 256) WS[i >> 6][i & 63] = W[i];
    if (tid < 64) { ksS[tid] = g_ksum[h*D + tid]; bS[tid] = b[tid]; }
    __syncthreads();
    for (int rr = 0; rr < 16; rr++) {
        int l = chunk*128 + rr*8 + w;
        const float* qr = q + (l*H + h)*D;
        float q0 = qr[lane], q1 = qr[lane + 32];
        float mx = fmaxf(q0, q1);
        #pragma unroll
        for (int o = 16; o > 0; o >>= 1) mx = fmaxf(mx, __shfl_xor_sync(0xffffffffu, mx, o));
        float e0 = __expf(q0 - mx), e1 = __expf(q1 - mx);
        float ssum = e0 + e1;
        #pragma unroll
        for (int o = 16; o > 0; o >>= 1) ssum += __shfl_xor_sync(0xffffffffu, ssum, o);
        float inv = 1.f / ssum;
        float f0 = e0*inv, f1 = e1*inv;
        qfmS[w][lane] = f0; qfmS[w][lane+32] = f1;
        float dn = f0*ksS[lane] + f1*ksS[lane+32];
        #pragma unroll
        for (int o = 16; o > 0; o >>= 1) dn += __shfl_xor_sync(0xffffffffu, dn, o);
        dn += 1e-6f;
        __syncwarp();
        float t0 = 0.f, t1 = 0.f;
        #pragma unroll
        for (int d = 0; d < 64; d++) {
            float qf = qfmS[w][d];
            t0 += qf * kvS[d][lane];
            t1 += qf * kvS[d][lane + 32];
        }
        float invdn = 1.f / dn;
        tmpS[w][lane] = t0*invdn; tmpS[w][lane+32] = t1*invdn;
        __syncwarp();
        float o0 = bS[lane], o1 = bS[lane + 32];
        #pragma unroll
        for (int e = 0; e < 64; e++) {
            float tv = tmpS[w][e];
            o0 += tv * WS[lane][e];
            o1 += tv * WS[lane + 32][e];
        }
        float* op = out + (l*H + h)*D;
        op[lane]      += o0;
        op[lane + 32] += o1;
    }
}

extern "C" void kernel_launch(void* const* d_in, const int* in_sizes, int n_in,
                              void* d_out, int out_size) {
    const float* q = (const float*)d_in[0];
    const float* k = (const float*)d_in[1];
    const float* v = (const float*)d_in[2];
    const float* W = (const float*)d_in[3];
    const float* b = (const float*)d_in[4];
    float* out = (float*)d_out;

    prep_kernel<<<dim3(H, 1 + M + NBLK), 256>>>(q, k);
    scoretopk_kernel<<<dim3(H, M/16), 256>>>();
    convert_kv_kernel<<<dim3(H, NBLK), 128>>>(k, v);
    sparse_attn_mma<<<dim3(H, M), 128>>>(q, out);
    kvsum_partial_kernel<<<dim3(H, NCH), 256>>>(k, v);
    reduce_kv_kernel<<<H, 256>>>();
    linear_out_kernel<<<dim3(H, 64), 256>>>(q, W, b, out);
}

// round 12
// speedup vs baseline: 2.7714x; 1.2655x over previous
#include <cuda_runtime.h>
#include <cuda_bf16.h>
#include <math.h>
#include <stdint.h>

#define H 16
#define D 64
#define L 8192
#define M 128
#define NBLK 256
#define T 25
#define NCH 32

#define PADK 72   // K smem row elems (144 B): ldmatrix rows conflict-free
#define PADV 40   // Vt smem row elems (80 B): conflict-free

__device__ float g_km[H*D];
__device__ float g_pq[H*M*D];
__device__ float g_pk[H*NBLK*D];
__device__ int   g_lut[H*M*T];
__device__ float g_kv_part[NCH*H*D*D];
__device__ float g_ks_part[NCH*H*D];
__device__ float g_kvW[H*D*D];    // kvsum @ W^T, layout [d][j]
__device__ float g_ksum[H*D];
// dense gmem layout: K block = 32x64, Vt block = 64x32 (pads only in smem)
__device__ __nv_bfloat16 g_kch[(size_t)H*NBLK*32*64];
__device__ __nv_bfloat16 g_kcl[(size_t)H*NBLK*32*64];
__device__ __nv_bfloat16 g_vth[(size_t)H*NBLK*64*32];
__device__ __nv_bfloat16 g_vtl[(size_t)H*NBLK*64*32];

// ---------------- helpers ----------------
__device__ __forceinline__ uint32_t smem_u32(const void* p) {
    return (uint32_t)__cvta_generic_to_shared(p);
}
__device__ __forceinline__ void cp16(uint32_t saddr, const void* gaddr) {
    asm volatile("cp.async.cg.shared.global [%0], [%1], 16;" :: "r"(saddr), "l"(gaddr));
}
#define CP_COMMIT() asm volatile("cp.async.commit_group;" ::: "memory")
#define CP_WAIT(n)  asm volatile("cp.async.wait_group %0;" :: "n"(n) : "memory")

__device__ __forceinline__ void mma16816(float* c, const uint32_t* a, uint32_t b0, uint32_t b1) {
    asm volatile(
        "mma.sync.aligned.m16n8k16.row.col.f32.bf16.bf16.f32 "
        "{%0,%1,%2,%3}, {%4,%5,%6,%7}, {%8,%9}, {%0,%1,%2,%3};"
        : "+f"(c[0]), "+f"(c[1]), "+f"(c[2]), "+f"(c[3])
        : "r"(a[0]), "r"(a[1]), "r"(a[2]), "r"(a[3]), "r"(b0), "r"(b1));
}
__device__ __forceinline__ void ldmx4(uint32_t& r0, uint32_t& r1, uint32_t& r2, uint32_t& r3,
                                      uint32_t addr) {
    asm volatile("ldmatrix.sync.aligned.m8n8.x4.shared.b16 {%0,%1,%2,%3}, [%4];"
                 : "=r"(r0), "=r"(r1), "=r"(r2), "=r"(r3) : "r"(addr));
}
__device__ __forceinline__ void split_pair(float a, float b, uint32_t& hi, uint32_t& lo) {
    __nv_bfloat16 ha = __float2bfloat16(a);
    __nv_bfloat16 hb = __float2bfloat16(b);
    __nv_bfloat162 hp; hp.x = ha; hp.y = hb;
    __nv_bfloat162 lp; lp.x = __float2bfloat16(a - __bfloat162float(ha));
    lp.y = __float2bfloat16(b - __bfloat162float(hb));
    hi = *(uint32_t*)&hp; lo = *(uint32_t*)&lp;
}

// ===== prep: pooled_q (y<M), pooled_k uncentered (y>=M); k read ONCE =====
__global__ __launch_bounds__(256) void prep_kernel(const float* __restrict__ q,
                                                   const float* __restrict__ k) {
    int h = blockIdx.x, y = blockIdx.y;
    int tid = threadIdx.x;
    __shared__ float part[256];
    int d = tid & 63, sub = tid >> 6;
    if (y < M) {
        float s = 0.f;
        for (int i = sub; i < 64; i += 4) s += q[((y*64 + i)*H + h)*D + d];
        part[tid] = s;
        __syncthreads();
        if (tid < 64)
            g_pq[(h*M + y)*D + tid] = (part[tid] + part[tid+64] + part[tid+128] + part[tid+192]) * (1.0f/64.0f);
    } else {
        int n = y - M;
        float s = 0.f;
        for (int i = sub; i < 32; i += 4) s += k[((n*32 + i)*H + h)*D + d];
        part[tid] = s;
        __syncthreads();
        if (tid < 64)
            g_pk[(h*NBLK + n)*D + tid] = (part[tid] + part[tid+64] + part[tid+128] + part[tid+192]) * (1.0f/32.0f);
    }
}
// km = mean over n of pooled_k (exact: uniform 32-row blocks)
__global__ __launch_bounds__(64) void km_from_pk_kernel() {
    int h = blockIdx.x, d = threadIdx.x;
    float s = 0.f;
    for (int n = 0; n < NBLK; n++) s += g_pk[(h*NBLK + n)*D + d];
    g_km[h*D + d] = s * (1.0f/NBLK);
}

// ===== fused score + topk: 16 m per block =====
__global__ __launch_bounds__(256) void scoretopk_kernel() {
    int h = blockIdx.x, mg = blockIdx.y * 16;
    __shared__ float pq[16][64];
    __shared__ float kmS[64];
    __shared__ float corr[16];
    __shared__ float sc[16][NBLK];
    int tid = threadIdx.x;
    for (int i = tid; i < 16*64; i += 256)
        pq[i >> 6][i & 63] = g_pq[(h*M + mg + (i >> 6))*D + (i & 63)];
    if (tid < 64) kmS[tid] = g_km[h*D + tid];
    __syncthreads();
    if (tid < 16) {
        float s = 0.f;
        #pragma unroll
        for (int d = 0; d < 64; d++) s += pq[tid][d] * kmS[d];
        corr[tid] = s;
    }
    __syncthreads();
    const float4* pk = (const float4*)(g_pk + (h*NBLK + tid)*D);
    float acc[16];
    #pragma unroll
    for (int mm = 0; mm < 16; mm++) acc[mm] = 0.f;
    #pragma unroll
    for (int ch = 0; ch < 4; ch++) {
        float4 kv[4];
        #pragma unroll
        for (int i = 0; i < 4; i++) kv[i] = pk[ch*4 + i];
        #pragma unroll
        for (int mm = 0; mm < 16; mm++) {
            float s = 0.f;
            #pragma unroll
            for (int i = 0; i < 4; i++) {
                float4 qv = *(const float4*)(&pq[mm][ch*16 + i*4]);
                s += qv.x*kv[i].x + qv.y*kv[i].y + qv.z*kv[i].z + qv.w*kv[i].w;
            }
            acc[mm] += s;
        }
    }
    #pragma unroll
    for (int mm = 0; mm < 16; mm++) sc[mm][tid] = acc[mm] - corr[mm];
    __syncthreads();
    int w = tid >> 5, lane = tid & 31;
    for (int s2 = 0; s2 < 2; s2++) {
        int mloc = w*2 + s2;
        float v[8];
        #pragma unroll
        for (int j = 0; j < 8; j++) v[j] = sc[mloc][j*32 + lane];
        int sel[T];
        for (int t = 0; t < T; t++) {
            float bv = -INFINITY; int bi = 1 << 30;
            #pragma unroll
            for (int j = 0; j < 8; j++)
                if (v[j] > bv) { bv = v[j]; bi = j*32 + lane; }
            #pragma unroll
            for (int off = 16; off > 0; off >>= 1) {
                float ov = __shfl_xor_sync(0xffffffffu, bv, off);
                int   oi = __shfl_xor_sync(0xffffffffu, bi, off);
                if (ov > bv || (ov == bv && oi < bi)) { bv = ov; bi = oi; }
            }
            sel[t] = bi;
            if ((bi & 31) == lane) v[bi >> 5] = -INFINITY;
        }
        if (lane == 0) {
            for (int a = 1; a < T; a++) {
                int key = sel[a]; int b = a - 1;
                while (b >= 0 && sel[b] > key) { sel[b+1] = sel[b]; b--; }
                sel[b+1] = key;
            }
            for (int t = 0; t < T; t++) g_lut[(h*M + mg + mloc)*T + t] = sel[t];
        }
    }
}

// ===== precompute centered+split K (dense 32x64), split+transposed V (dense 64x32) =====
__global__ __launch_bounds__(128) void convert_kv_kernel(const float* __restrict__ k,
                                                         const float* __restrict__ v) {
    int h = blockIdx.x, n = blockIdx.y;
    int tid = threadIdx.x;
    __shared__ float vS[32][65];
    {
        int vr = tid >> 2, vp = tid & 3;
        const float4* src = (const float4*)(v + ((size_t)(n*32 + vr)*H + h)*D + vp*16);
        #pragma unroll
        for (int i = 0; i < 4; i++) {
            float4 f = src[i];
            vS[vr][vp*16 + 4*i + 0] = f.x;
            vS[vr][vp*16 + 4*i + 1] = f.y;
            vS[vr][vp*16 + 4*i + 2] = f.z;
            vS[vr][vp*16 + 4*i + 3] = f.w;
        }
    }
    {
        int kr = tid >> 2, kp = tid & 3;
        const float4* src = (const float4*)(k + ((size_t)(n*32 + kr)*H + h)*D + kp*16);
        float xs[16];
        #pragma unroll
        for (int i = 0; i < 4; i++) {
            float4 f = src[i];
            xs[4*i+0] = f.x - g_km[h*D + kp*16 + 4*i+0];
            xs[4*i+1] = f.y - g_km[h*D + kp*16 + 4*i+1];
            xs[4*i+2] = f.z - g_km[h*D + kp*16 + 4*i+2];
            xs[4*i+3] = f.w - g_km[h*D + kp*16 + 4*i+3];
        }
        uint32_t hi[8], lo[8];
        #pragma unroll
        for (int j = 0; j < 8; j++) split_pair(xs[2*j], xs[2*j+1], hi[j], lo[j]);
        size_t off = ((size_t)(h*NBLK + n)*32 + kr)*64 + kp*16;
        *(uint4*)(g_kch + off)     = make_uint4(hi[0],hi[1],hi[2],hi[3]);
        *(uint4*)(g_kch + off + 8) = make_uint4(hi[4],hi[5],hi[6],hi[7]);
        *(uint4*)(g_kcl + off)     = make_uint4(lo[0],lo[1],lo[2],lo[3]);
        *(uint4*)(g_kcl + off + 8) = make_uint4(lo[4],lo[5],lo[6],lo[7]);
    }
    __syncthreads();
    {
        int d = tid & 63, part = tid >> 6;
        uint32_t hi[8], lo[8];
        #pragma unroll
        for (int j = 0; j < 8; j++) {
            float a = vS[part*16 + 2*j][d];
            float b = vS[part*16 + 2*j + 1][d];
            split_pair(a, b, hi[j], lo[j]);
        }
        size_t off = ((size_t)(h*NBLK + n)*64 + d)*32 + part*16;
        *(uint4*)(g_vth + off)     = make_uint4(hi[0],hi[1],hi[2],hi[3]);
        *(uint4*)(g_vth + off + 8) = make_uint4(hi[4],hi[5],hi[6],hi[7]);
        *(uint4*)(g_vtl + off)     = make_uint4(lo[0],lo[1],lo[2],lo[3]);
        *(uint4*)(g_vtl + off + 8) = make_uint4(lo[4],lo[5],lo[6],lo[7]);
    }
}

// ============ block-sparse attention: cp.async + ldmatrix + mma.sync ============
__global__ __launch_bounds__(128) void sparse_attn_mma(
    const float* __restrict__ q, float* __restrict__ out)
{
    __shared__ __align__(16) __nv_bfloat16 sKh[2][32*PADK];
    __shared__ __align__(16) __nv_bfloat16 sKl[2][32*PADK];
    __shared__ __align__(16) __nv_bfloat16 sVh[2][64*PADV];
    __shared__ __align__(16) __nv_bfloat16 sVl[2][64*PADV];

    const int h = blockIdx.x, m = blockIdx.y;
    const int tid = threadIdx.x;
    const int w = tid >> 5, lane = tid & 31;
    const int g = lane >> 2, tc = lane & 3;
    const int lr = lane & 7, quad = lane >> 3;
    const int rowoff = ((quad >> 1) << 3) + lr;
    const int koff = (quad & 1) << 3;

    uint32_t aQh[4][4], aQl[4][4];
    {
        int r0 = m*64 + w*16 + g;
        const float* q0 = q + ((size_t)r0*H + h)*D;
        const float* q1 = q + ((size_t)(r0+8)*H + h)*D;
        #pragma unroll
        for (int kt = 0; kt < 4; kt++) {
            int c0 = kt*16 + tc*2;
            float2 f;
            f = *(const float2*)(q0 + c0);     split_pair(f.x, f.y, aQh[kt][0], aQl[kt][0]);
            f = *(const float2*)(q1 + c0);     split_pair(f.x, f.y, aQh[kt][1], aQl[kt][1]);
            f = *(const float2*)(q0 + c0 + 8); split_pair(f.x, f.y, aQh[kt][2], aQl[kt][2]);
            f = *(const float2*)(q1 + c0 + 8); split_pair(f.x, f.y, aQh[kt][3], aQl[kt][3]);
        }
    }

    const int krow = tid >> 2, kseg = tid & 3;
    const int vrow = tid >> 1, vseg = tid & 1;
    const uint32_t ksm = (uint32_t)(krow*PADK + kseg*16)*2;
    const uint32_t vsm = (uint32_t)(vrow*PADV + vseg*16)*2;
    const size_t   kgo = (size_t)krow*64 + kseg*16;
    const size_t   vgo = (size_t)vrow*32 + vseg*16;
    const int* lut = g_lut + (h*M + m)*T;

    #define LOAD_STAGE(n_, buf_) do { \
        size_t kb = ((size_t)(h*NBLK + (n_)))*2048 + kgo; \
        size_t vb = ((size_t)(h*NBLK + (n_)))*2048 + vgo; \
        uint32_t skh = smem_u32(&sKh[buf_][0]) + ksm; \
        uint32_t skl = smem_u32(&sKl[buf_][0]) + ksm; \
        uint32_t svh = smem_u32(&sVh[buf_][0]) + vsm; \
        uint32_t svl = smem_u32(&sVl[buf_][0]) + vsm; \
        cp16(skh,      g_kch + kb); \
        cp16(skh + 16, g_kch + kb + 8); \
        cp16(skl,      g_kcl + kb); \
        cp16(skl + 16, g_kcl + kb + 8); \
        cp16(svh,      g_vth + vb); \
        cp16(svh + 16, g_vth + vb + 8); \
        cp16(svl,      g_vtl + vb); \
        cp16(svl + 16, g_vtl + vb + 8); \
    } while (0)

    float o[8][4];
    #pragma unroll
    for (int a = 0; a < 8; a++)
        #pragma unroll
        for (int j = 0; j < 4; j++) o[a][j] = 0.f;
    float lrow0 = 0.f, lrow1 = 0.f;

    LOAD_STAGE(lut[0], 0);
    CP_COMMIT();

    for (int t = 0; t < T; t++) {
        int buf = t & 1;
        if (t + 1 < T) {
            LOAD_STAGE(lut[t+1], (t+1) & 1);
            CP_COMMIT();
            CP_WAIT(1);
        } else {
            CP_WAIT(0);
        }
        __syncthreads();

        const uint32_t aKh = smem_u32(&sKh[buf][0]) + (uint32_t)(rowoff*PADK + koff)*2;
        const uint32_t aKl = smem_u32(&sKl[buf][0]) + (uint32_t)(rowoff*PADK + koff)*2;
        const uint32_t aVh = smem_u32(&sVh[buf][0]) + (uint32_t)(rowoff*PADV + koff)*2;
        const uint32_t aVl = smem_u32(&sVl[buf][0]) + (uint32_t)(rowoff*PADV + koff)*2;

        float c[4][4];
        #pragma unroll
        for (int nt = 0; nt < 4; nt++)
            #pragma unroll
            for (int j = 0; j < 4; j++) c[nt][j] = 0.f;
        #pragma unroll
        for (int ntp = 0; ntp < 2; ntp++) {
            #pragma unroll
            for (int kt = 0; kt < 4; kt++) {
                uint32_t off = (uint32_t)(ntp*16*PADK + kt*16)*2;
                uint32_t h0,h1,h2,h3, l0,l1,l2,l3;
                ldmx4(h0,h1,h2,h3, aKh + off);
                ldmx4(l0,l1,l2,l3, aKl + off);
                mma16816(c[2*ntp],   aQh[kt], h0, h1);
                mma16816(c[2*ntp],   aQl[kt], h0, h1);
                mma16816(c[2*ntp],   aQh[kt], l0, l1);
                mma16816(c[2*ntp+1], aQh[kt], h2, h3);
                mma16816(c[2*ntp+1], aQl[kt], h2, h3);
                mma16816(c[2*ntp+1], aQh[kt], l2, l3);
            }
        }
        float pr[4][4];
        float rs0 = 0.f, rs1 = 0.f;
        #pragma unroll
        for (int nt = 0; nt < 4; nt++) {
            #pragma unroll
            for (int j = 0; j < 4; j++) pr[nt][j] = __expf(c[nt][j] * 0.125f);
            rs0 += pr[nt][0] + pr[nt][1];
            rs1 += pr[nt][2] + pr[nt][3];
        }
        rs0 += __shfl_xor_sync(0xffffffffu, rs0, 1);
        rs0 += __shfl_xor_sync(0xffffffffu, rs0, 2);
        rs1 += __shfl_xor_sync(0xffffffffu, rs1, 1);
        rs1 += __shfl_xor_sync(0xffffffffu, rs1, 2);
        lrow0 += rs0; lrow1 += rs1;

        uint32_t aPh[2][4], aPl[2][4];
        #pragma unroll
        for (int kp2 = 0; kp2 < 2; kp2++) {
            split_pair(pr[2*kp2][0],   pr[2*kp2][1],   aPh[kp2][0], aPl[kp2][0]);
            split_pair(pr[2*kp2][2],   pr[2*kp2][3],   aPh[kp2][1], aPl[kp2][1]);
            split_pair(pr[2*kp2+1][0], pr[2*kp2+1][1], aPh[kp2][2], aPl[kp2][2]);
            split_pair(pr[2*kp2+1][2], pr[2*kp2+1][3], aPh[kp2][3], aPl[kp2][3]);
        }
        #pragma unroll
        for (int nvp = 0; nvp < 4; nvp++) {
            #pragma unroll
            for (int kp2 = 0; kp2 < 2; kp2++) {
                uint32_t off = (uint32_t)(nvp*16*PADV + kp2*16)*2;
                uint32_t h0,h1,h2,h3, l0,l1,l2,l3;
                ldmx4(h0,h1,h2,h3, aVh + off);
                ldmx4(l0,l1,l2,l3, aVl + off);
                mma16816(o[2*nvp],   aPh[kp2], h0, h1);
                mma16816(o[2*nvp],   aPl[kp2], h0, h1);
                mma16816(o[2*nvp],   aPh[kp2], l0, l1);
                mma16816(o[2*nvp+1], aPh[kp2], h2, h3);
                mma16816(o[2*nvp+1], aPl[kp2], h2, h3);
                mma16816(o[2*nvp+1], aPh[kp2], l2, l3);
            }
        }
        __syncthreads();
    }

    float inv0 = 1.f / lrow0;
    float inv1 = 1.f / lrow1;
    int r0 = m*64 + w*16 + g;
    float* out0 = out + ((size_t)r0*H + h)*D;
    float* out1 = out + ((size_t)(r0+8)*H + h)*D;
    #pragma unroll
    for (int nv = 0; nv < 8; nv++) {
        int cc = nv*8 + tc*2;
        *(float2*)(out0 + cc) = make_float2(o[nv][0]*inv0, o[nv][1]*inv0);
        *(float2*)(out1 + cc) = make_float2(o[nv][2]*inv1, o[nv][3]*inv1);
    }
    #undef LOAD_STAGE
}

// ====== kvsum partials: NCH=32 chunks of 256 rows ======
__global__ __launch_bounds__(256) void kvsum_partial_kernel(const float* __restrict__ k,
                                                            const float* __restrict__ v) {
    int h = blockIdx.x, c = blockIdx.y;
    __shared__ float kfS[8][64];
    __shared__ float vS[8][64];
    int tid = threadIdx.x, w = tid >> 5, lane = tid & 31;
    int e = tid & 63, g = tid >> 6;
    int d0 = g * 16;
    float acc[16];
    #pragma unroll
    for (int j = 0; j < 16; j++) acc[j] = 0.f;
    float ks_acc = 0.f;
    for (int sIt = 0; sIt < 32; sIt++) {
        int l = c*256 + sIt*8 + w;
        __syncthreads();
        const float* kr = k + (l*H + h)*D;
        const float* vr = v + (l*H + h)*D;
        float e0 = __expf(kr[lane]), e1 = __expf(kr[lane + 32]);
        float sm = e0 + e1;
        #pragma unroll
        for (int o = 16; o > 0; o >>= 1) sm += __shfl_xor_sync(0xffffffffu, sm, o);
        float inv = 1.f / sm;
        kfS[w][lane] = e0*inv; kfS[w][lane+32] = e1*inv;
        vS[w][lane] = vr[lane]; vS[w][lane+32] = vr[lane+32];
        __syncthreads();
        #pragma unroll
        for (int rr = 0; rr < 8; rr++) {
            float ve = vS[rr][e];
            #pragma unroll
            for (int j = 0; j < 16; j++) acc[j] += kfS[rr][d0 + j] * ve;
        }
        if (g == 0) {
            #pragma unroll
            for (int rr = 0; rr < 8; rr++) ks_acc += kfS[rr][e];
        }
    }
    float* dst = g_kv_part + (c*H + h)*D*D;
    #pragma unroll
    for (int j = 0; j < 16; j++) dst[(d0 + j)*D + e] = acc[j];
    if (g == 0) g_ks_part[(c*H + h)*D + e] = ks_acc;
}

// ====== reduce partials + fold projection: kvW = kvsum @ W^T ======
__global__ __launch_bounds__(256) void reduce_kv_kernel(const float* __restrict__ W) {
    int h = blockIdx.x;
    __shared__ float kvS[64][64];
    __shared__ float WS[64][65];
    int tid = threadIdx.x;
    for (int i = tid; i < D*D; i += 256) {
        float s = 0.f;
        for (int c = 0; c < NCH; c++) s += g_kv_part[(c*H + h)*D*D + i];
        kvS[i >> 6][i & 63] = s;
    }
    for (int i = tid; i < D*D; i += 256) WS[i >> 6][i & 63] = W[i];
    for (int i = tid; i < D; i += 256) {
        float s = 0.f;
        for (int c = 0; c < NCH; c++) s += g_ks_part[(c*H + h)*D + i];
        g_ksum[h*D + i] = s;
    }
    __syncthreads();
    // kvW[d][j] = sum_e kvsum[d][e] * W[j][e]
    int j = tid & 63, dg = tid >> 6;   // 4 d-groups of 16
    #pragma unroll
    for (int dd = 0; dd < 16; dd++) {
        int d = dg*16 + dd;
        float s = 0.f;
        #pragma unroll
        for (int e = 0; e < 64; e++) s += kvS[d][e] * WS[j][e];
        g_kvW[h*D*D + d*64 + j] = s;
    }
}

// ====== linear branch: out += (q_fm @ kvW)/denom + b ======
__global__ __launch_bounds__(256) void linear_out_kernel(const float* __restrict__ q,
                                                         const float* __restrict__ b,
                                                         float* __restrict__ out) {
    int h = blockIdx.x, chunk = blockIdx.y;
    __shared__ float kvS[64][64];
    __shared__ float ksS[64];
    __shared__ float bS[64];
    __shared__ float qfmS[8][64];
    int tid = threadIdx.x, w = tid >> 5, lane = tid & 31;
    for (int i = tid; i < 4096; i += 256) kvS[i >> 6][i & 63] = g_kvW[h*D*D + i];
    if (tid < 64) { ksS[tid] = g_ksum[h*D + tid]; bS[tid] = b[tid]; }
    __syncthreads();
    for (int rr = 0; rr < 16; rr++) {
        int l = chunk*128 + rr*8 + w;
        const float* qr = q + (l*H + h)*D;
        float q0 = qr[lane], q1 = qr[lane + 32];
        float mx = fmaxf(q0, q1);
        #pragma unroll
        for (int o = 16; o > 0; o >>= 1) mx = fmaxf(mx, __shfl_xor_sync(0xffffffffu, mx, o));
        float e0 = __expf(q0 - mx), e1 = __expf(q1 - mx);
        float ssum = e0 + e1;
        #pragma unroll
        for (int o = 16; o > 0; o >>= 1) ssum += __shfl_xor_sync(0xffffffffu, ssum, o);
        float inv = 1.f / ssum;
        float f0 = e0*inv, f1 = e1*inv;
        qfmS[w][lane] = f0; qfmS[w][lane+32] = f1;
        float dn = f0*ksS[lane] + f1*ksS[lane+32];
        #pragma unroll
        for (int o = 16; o > 0; o >>= 1) dn += __shfl_xor_sync(0xffffffffu, dn, o);
        dn += 1e-6f;
        __syncwarp();
        float t0 = 0.f, t1 = 0.f;
        #pragma unroll
        for (int d = 0; d < 64; d++) {
            float qf = qfmS[w][d];
            t0 += qf * kvS[d][lane];
            t1 += qf * kvS[d][lane + 32];
        }
        float invdn = 1.f / dn;
        float* op = out + (l*H + h)*D;
        op[lane]      += t0*invdn + bS[lane];
        op[lane + 32] += t1*invdn + bS[lane + 32];
    }
}

extern "C" void kernel_launch(void* const* d_in, const int* in_sizes, int n_in,
                              void* d_out, int out_size) {
    const float* q = (const float*)d_in[0];
    const float* k = (const float*)d_in[1];
    const float* v = (const float*)d_in[2];
    const float* W = (const float*)d_in[3];
    const float* b = (const float*)d_in[4];
    float* out = (float*)d_out;

    prep_kernel<<<dim3(H, M + NBLK), 256>>>(q, k);
    km_from_pk_kernel<<<H, 64>>>();
    scoretopk_kernel<<<dim3(H, M/16), 256>>>();
    convert_kv_kernel<<<dim3(H, NBLK), 128>>>(k, v);
    sparse_attn_mma<<<dim3(H, M), 128>>>(q, out);
    kvsum_partial_kernel<<<dim3(H, NCH), 256>>>(k, v);
    reduce_kv_kernel<<<H, 256>>>(W);
    linear_out_kernel<<<dim3(H, 64), 256>>>(q, b, out);
}

// round 14
// speedup vs baseline: 3.2521x; 1.1735x over previous
#include <cuda_runtime.h>
#include <cuda_bf16.h>
#include <math.h>
#include <stdint.h>

#define H 16
#define D 64
#define L 8192
#define M 128
#define NBLK 256
#define T 25
#define NCH 32

#define PADK 72   // K smem row elems (144 B): ldmatrix rows conflict-free
#define PADV 40   // Vt smem row elems (80 B): conflict-free
#define PADW 72   // kvW smem row elems (== PADK, reuses K smem + addressing)

__device__ float g_km[H*D];
__device__ float g_pq[H*M*D];
__device__ float g_pk[H*NBLK*D];
__device__ int   g_lut[H*M*T];
__device__ float g_kv_part[NCH*H*D*D];
__device__ float g_ks_part[NCH*H*D];
__device__ float g_ksum[H*D];
__device__ __nv_bfloat16 g_kvWh[H*D*D];   // (kvsum@W^T)^T split hi, layout [j][d]
__device__ __nv_bfloat16 g_kvWl[H*D*D];   // split lo
// dense gmem layout: K block = 32x64, Vt block = 64x32 (pads only in smem)
__device__ __nv_bfloat16 g_kch[(size_t)H*NBLK*32*64];
__device__ __nv_bfloat16 g_kcl[(size_t)H*NBLK*32*64];
__device__ __nv_bfloat16 g_vth[(size_t)H*NBLK*64*32];
__device__ __nv_bfloat16 g_vtl[(size_t)H*NBLK*64*32];

// ---------------- helpers ----------------
__device__ __forceinline__ uint32_t smem_u32(const void* p) {
    return (uint32_t)__cvta_generic_to_shared(p);
}
__device__ __forceinline__ void cp16(uint32_t saddr, const void* gaddr) {
    asm volatile("cp.async.cg.shared.global [%0], [%1], 16;" :: "r"(saddr), "l"(gaddr));
}
#define CP_COMMIT() asm volatile("cp.async.commit_group;" ::: "memory")
#define CP_WAIT(n)  asm volatile("cp.async.wait_group %0;" :: "n"(n) : "memory")

__device__ __forceinline__ void mma16816(float* c, const uint32_t* a, uint32_t b0, uint32_t b1) {
    asm volatile(
        "mma.sync.aligned.m16n8k16.row.col.f32.bf16.bf16.f32 "
        "{%0,%1,%2,%3}, {%4,%5,%6,%7}, {%8,%9}, {%0,%1,%2,%3};"
        : "+f"(c[0]), "+f"(c[1]), "+f"(c[2]), "+f"(c[3])
        : "r"(a[0]), "r"(a[1]), "r"(a[2]), "r"(a[3]), "r"(b0), "r"(b1));
}
__device__ __forceinline__ void ldmx4(uint32_t& r0, uint32_t& r1, uint32_t& r2, uint32_t& r3,
                                      uint32_t addr) {
    asm volatile("ldmatrix.sync.aligned.m8n8.x4.shared.b16 {%0,%1,%2,%3}, [%4];"
                 : "=r"(r0), "=r"(r1), "=r"(r2), "=r"(r3) : "r"(addr));
}
__device__ __forceinline__ void split_pair(float a, float b, uint32_t& hi, uint32_t& lo) {
    __nv_bfloat16 ha = __float2bfloat16(a);
    __nv_bfloat16 hb = __float2bfloat16(b);
    __nv_bfloat162 hp; hp.x = ha; hp.y = hb;
    __nv_bfloat162 lp; lp.x = __float2bfloat16(a - __bfloat162float(ha));
    lp.y = __float2bfloat16(b - __bfloat162float(hb));
    hi = *(uint32_t*)&hp; lo = *(uint32_t*)&lp;
}

// ===== prep: pooled_q (y<M), pooled_k uncentered (y>=M); k read ONCE =====
__global__ __launch_bounds__(256) void prep_kernel(const float* __restrict__ q,
                                                   const float* __restrict__ k) {
    int h = blockIdx.x, y = blockIdx.y;
    int tid = threadIdx.x;
    __shared__ float part[256];
    int d = tid & 63, sub = tid >> 6;
    if (y < M) {
        float s = 0.f;
        for (int i = sub; i < 64; i += 4) s += q[((y*64 + i)*H + h)*D + d];
        part[tid] = s;
        __syncthreads();
        if (tid < 64)
            g_pq[(h*M + y)*D + tid] = (part[tid] + part[tid+64] + part[tid+128] + part[tid+192]) * (1.0f/64.0f);
    } else {
        int n = y - M;
        float s = 0.f;
        for (int i = sub; i < 32; i += 4) s += k[((n*32 + i)*H + h)*D + d];
        part[tid] = s;
        __syncthreads();
        if (tid < 64)
            g_pk[(h*NBLK + n)*D + tid] = (part[tid] + part[tid+64] + part[tid+128] + part[tid+192]) * (1.0f/32.0f);
    }
}
__global__ __launch_bounds__(64) void km_from_pk_kernel() {
    int h = blockIdx.x, d = threadIdx.x;
    float s = 0.f;
    for (int n = 0; n < NBLK; n++) s += g_pk[(h*NBLK + n)*D + d];
    g_km[h*D + d] = s * (1.0f/NBLK);
}

// ===== fused score + topk: 16 m per block =====
__global__ __launch_bounds__(256) void scoretopk_kernel() {
    int h = blockIdx.x, mg = blockIdx.y * 16;
    __shared__ float pq[16][64];
    __shared__ float kmS[64];
    __shared__ float corr[16];
    __shared__ float sc[16][NBLK];
    int tid = threadIdx.x;
    for (int i = tid; i < 16*64; i += 256)
        pq[i >> 6][i & 63] = g_pq[(h*M + mg + (i >> 6))*D + (i & 63)];
    if (tid < 64) kmS[tid] = g_km[h*D + tid];
    __syncthreads();
    if (tid < 16) {
        float s = 0.f;
        #pragma unroll
        for (int d = 0; d < 64; d++) s += pq[tid][d] * kmS[d];
        corr[tid] = s;
    }
    __syncthreads();
    const float4* pk = (const float4*)(g_pk + (h*NBLK + tid)*D);
    float acc[16];
    #pragma unroll
    for (int mm = 0; mm < 16; mm++) acc[mm] = 0.f;
    #pragma unroll
    for (int ch = 0; ch < 4; ch++) {
        float4 kv[4];
        #pragma unroll
        for (int i = 0; i < 4; i++) kv[i] = pk[ch*4 + i];
        #pragma unroll
        for (int mm = 0; mm < 16; mm++) {
            float s = 0.f;
            #pragma unroll
            for (int i = 0; i < 4; i++) {
                float4 qv = *(const float4*)(&pq[mm][ch*16 + i*4]);
                s += qv.x*kv[i].x + qv.y*kv[i].y + qv.z*kv[i].z + qv.w*kv[i].w;
            }
            acc[mm] += s;
        }
    }
    #pragma unroll
    for (int mm = 0; mm < 16; mm++) sc[mm][tid] = acc[mm] - corr[mm];
    __syncthreads();
    int w = tid >> 5, lane = tid & 31;
    for (int s2 = 0; s2 < 2; s2++) {
        int mloc = w*2 + s2;
        float v[8];
        #pragma unroll
        for (int j = 0; j < 8; j++) v[j] = sc[mloc][j*32 + lane];
        int sel[T];
        for (int t = 0; t < T; t++) {
            float bv = -INFINITY; int bi = 1 << 30;
            #pragma unroll
            for (int j = 0; j < 8; j++)
                if (v[j] > bv) { bv = v[j]; bi = j*32 + lane; }
            #pragma unroll
            for (int off = 16; off > 0; off >>= 1) {
                float ov = __shfl_xor_sync(0xffffffffu, bv, off);
                int   oi = __shfl_xor_sync(0xffffffffu, bi, off);
                if (ov > bv || (ov == bv && oi < bi)) { bv = ov; bi = oi; }
            }
            sel[t] = bi;
            if ((bi & 31) == lane) v[bi >> 5] = -INFINITY;
        }
        if (lane == 0) {
            for (int a = 1; a < T; a++) {
                int key = sel[a]; int b = a - 1;
                while (b >= 0 && sel[b] > key) { sel[b+1] = sel[b]; b--; }
                sel[b+1] = key;
            }
            for (int t = 0; t < T; t++) g_lut[(h*M + mg + mloc)*T + t] = sel[t];
        }
    }
}

// ===== precompute centered+split K (dense 32x64), split+transposed V (dense 64x32) =====
__global__ __launch_bounds__(128) void convert_kv_kernel(const float* __restrict__ k,
                                                         const float* __restrict__ v) {
    int h = blockIdx.x, n = blockIdx.y;
    int tid = threadIdx.x;
    __shared__ float vS[32][65];
    {
        int vr = tid >> 2, vp = tid & 3;
        const float4* src = (const float4*)(v + ((size_t)(n*32 + vr)*H + h)*D + vp*16);
        #pragma unroll
        for (int i = 0; i < 4; i++) {
            float4 f = src[i];
            vS[vr][vp*16 + 4*i + 0] = f.x;
            vS[vr][vp*16 + 4*i + 1] = f.y;
            vS[vr][vp*16 + 4*i + 2] = f.z;
            vS[vr][vp*16 + 4*i + 3] = f.w;
        }
    }
    {
        int kr = tid >> 2, kp = tid & 3;
        const float4* src = (const float4*)(k + ((size_t)(n*32 + kr)*H + h)*D + kp*16);
        float xs[16];
        #pragma unroll
        for (int i = 0; i < 4; i++) {
            float4 f = src[i];
            xs[4*i+0] = f.x - g_km[h*D + kp*16 + 4*i+0];
            xs[4*i+1] = f.y - g_km[h*D + kp*16 + 4*i+1];
            xs[4*i+2] = f.z - g_km[h*D + kp*16 + 4*i+2];
            xs[4*i+3] = f.w - g_km[h*D + kp*16 + 4*i+3];
        }
        uint32_t hi[8], lo[8];
        #pragma unroll
        for (int j = 0; j < 8; j++) split_pair(xs[2*j], xs[2*j+1], hi[j], lo[j]);
        size_t off = ((size_t)(h*NBLK + n)*32 + kr)*64 + kp*16;
        *(uint4*)(g_kch + off)     = make_uint4(hi[0],hi[1],hi[2],hi[3]);
        *(uint4*)(g_kch + off + 8) = make_uint4(hi[4],hi[5],hi[6],hi[7]);
        *(uint4*)(g_kcl + off)     = make_uint4(lo[0],lo[1],lo[2],lo[3]);
        *(uint4*)(g_kcl + off + 8) = make_uint4(lo[4],lo[5],lo[6],lo[7]);
    }
    __syncthreads();
    {
        int d = tid & 63, part = tid >> 6;
        uint32_t hi[8], lo[8];
        #pragma unroll
        for (int j = 0; j < 8; j++) {
            float a = vS[part*16 + 2*j][d];
            float b = vS[part*16 + 2*j + 1][d];
            split_pair(a, b, hi[j], lo[j]);
        }
        size_t off = ((size_t)(h*NBLK + n)*64 + d)*32 + part*16;
        *(uint4*)(g_vth + off)     = make_uint4(hi[0],hi[1],hi[2],hi[3]);
        *(uint4*)(g_vth + off + 8) = make_uint4(hi[4],hi[5],hi[6],hi[7]);
        *(uint4*)(g_vtl + off)     = make_uint4(lo[0],lo[1],lo[2],lo[3]);
        *(uint4*)(g_vtl + off + 8) = make_uint4(lo[4],lo[5],lo[6],lo[7]);
    }
}

// ====== kvsum partials: NCH=32 chunks of 256 rows ======
__global__ __launch_bounds__(256) void kvsum_partial_kernel(const float* __restrict__ k,
                                                            const float* __restrict__ v) {
    int h = blockIdx.x, c = blockIdx.y;
    __shared__ float kfS[8][64];
    __shared__ float vS[8][64];
    int tid = threadIdx.x, w = tid >> 5, lane = tid & 31;
    int e = tid & 63, g = tid >> 6;
    int d0 = g * 16;
    float acc[16];
    #pragma unroll
    for (int j = 0; j < 16; j++) acc[j] = 0.f;
    float ks_acc = 0.f;
    for (int sIt = 0; sIt < 32; sIt++) {
        int l = c*256 + sIt*8 + w;
        __syncthreads();
        const float* kr = k + (l*H + h)*D;
        const float* vr = v + (l*H + h)*D;
        float e0 = __expf(kr[lane]), e1 = __expf(kr[lane + 32]);
        float sm = e0 + e1;
        #pragma unroll
        for (int o = 16; o > 0; o >>= 1) sm += __shfl_xor_sync(0xffffffffu, sm, o);
        float inv = 1.f / sm;
        kfS[w][lane] = e0*inv; kfS[w][lane+32] = e1*inv;
        vS[w][lane] = vr[lane]; vS[w][lane+32] = vr[lane+32];
        __syncthreads();
        #pragma unroll
        for (int rr = 0; rr < 8; rr++) {
            float ve = vS[rr][e];
            #pragma unroll
            for (int j = 0; j < 16; j++) acc[j] += kfS[rr][d0 + j] * ve;
        }
        if (g == 0) {
            #pragma unroll
            for (int rr = 0; rr < 8; rr++) ks_acc += kfS[rr][e];
        }
    }
    float* dst = g_kv_part + (c*H + h)*D*D;
    #pragma unroll
    for (int j = 0; j < 16; j++) dst[(d0 + j)*D + e] = acc[j];
    if (g == 0) g_ks_part[(c*H + h)*D + e] = ks_acc;
}

// ====== reduce partials + fold projection: kvW^T = (kvsum @ W^T)^T, bf16 split ======
__global__ __launch_bounds__(256) void reduce_kv_kernel(const float* __restrict__ W) {
    int h = blockIdx.x;
    __shared__ float kvS[64][64];
    __shared__ float WS[64][65];
    int tid = threadIdx.x;
    for (int i = tid; i < D*D; i += 256) {
        float s = 0.f;
        for (int c = 0; c < NCH; c++) s += g_kv_part[(c*H + h)*D*D + i];
        kvS[i >> 6][i & 63] = s;
    }
    for (int i = tid; i < D*D; i += 256) WS[i >> 6][i & 63] = W[i];
    for (int i = tid; i < D; i += 256) {
        float s = 0.f;
        for (int c = 0; c < NCH; c++) s += g_ks_part[(c*H + h)*D + i];
        g_ksum[h*D + i] = s;
    }
    __syncthreads();
    // kvW_t[j][d] = sum_e kvsum[d][e] * W[j][e], bf16 hi/lo split
    int j = tid & 63, dg = tid >> 6;
    #pragma unroll
    for (int dd = 0; dd < 16; dd++) {
        int d = dg*16 + dd;
        float s = 0.f;
        #pragma unroll
        for (int e = 0; e < 64; e++) s += kvS[d][e] * WS[j][e];
        __nv_bfloat16 hi = __float2bfloat16(s);
        __nv_bfloat16 lo = __float2bfloat16(s - __bfloat162float(hi));
        g_kvWh[h*D*D + j*64 + d] = hi;
        g_kvWl[h*D*D + j*64 + d] = lo;
    }
}

// ============ fused: linear-branch prologue (tensor core) + block-sparse attention ============
__global__ __launch_bounds__(128) void sparse_attn_mma(
    const float* __restrict__ q, const float* __restrict__ b, float* __restrict__ out)
{
    __shared__ __align__(16) __nv_bfloat16 sKh[2][32*PADK];   // prologue: kvWh [64][PADW]
    __shared__ __align__(16) __nv_bfloat16 sKl[2][32*PADK];   // prologue: kvWl
    __shared__ __align__(16) __nv_bfloat16 sVh[2][64*PADV];
    __shared__ __align__(16) __nv_bfloat16 sVl[2][64*PADV];
    __shared__ float ksumS[64];
    __shared__ float bS[64];

    const int h = blockIdx.x, m = blockIdx.y;
    const int tid = threadIdx.x;
    const int w = tid >> 5, lane = tid & 31;
    const int g = lane >> 2, tc = lane & 3;
    const int lr = lane & 7, quad = lane >> 3;
    const int rowoff = ((quad >> 1) << 3) + lr;
    const int koff = (quad & 1) << 3;

    const int r0 = m*64 + w*16 + g;
    float* out0 = out + ((size_t)r0*H + h)*D;
    float* out1 = out + ((size_t)(r0+8)*H + h)*D;

    // ---- kvW tiles -> K smem area (flat [64][PADW]) via cp.async ----
    {
        int r = tid >> 1, seg = tid & 1;
        uint32_t dh = smem_u32(&sKh[0][0]) + (uint32_t)(r*PADW + seg*32)*2;
        uint32_t dl = smem_u32(&sKl[0][0]) + (uint32_t)(r*PADW + seg*32)*2;
        size_t src = (size_t)h*D*D + (size_t)r*64 + seg*32;
        #pragma unroll
        for (int i = 0; i < 4; i++) {
            cp16(dh + i*16, g_kvWh + src + i*8);
            cp16(dl + i*16, g_kvWl + src + i*8);
        }
        CP_COMMIT();
    }
    if (tid < 64) { ksumS[tid] = g_ksum[h*D + tid]; bS[tid] = b[tid]; }
    __syncthreads();   // ksumS/bS visible

    // ---- Q fragments (persistent) + linear-branch A fragments (scaled exp(q)) ----
    uint32_t aQh[4][4], aQl[4][4];
    uint32_t aEh[4][4], aEl[4][4];
    #pragma unroll
    for (int ri = 0; ri < 2; ri++) {
        const float* qr = q + ((size_t)(r0 + ri*8)*H + h)*D;
        float exr[16];
        float se = 0.f, sd = 0.f;
        #pragma unroll
        for (int kt = 0; kt < 4; kt++) {
            int c0 = kt*16 + tc*2;
            float2 fa = *(const float2*)(qr + c0);
            float2 fb = *(const float2*)(qr + c0 + 8);
            split_pair(fa.x, fa.y, aQh[kt][ri],   aQl[kt][ri]);
            split_pair(fb.x, fb.y, aQh[kt][2+ri], aQl[kt][2+ri]);
            float e0 = __expf(fa.x), e1 = __expf(fa.y);
            float e2 = __expf(fb.x), e3 = __expf(fb.y);
            exr[kt*4+0] = e0; exr[kt*4+1] = e1; exr[kt*4+2] = e2; exr[kt*4+3] = e3;
            se += e0 + e1 + e2 + e3;
            sd += e0*ksumS[c0] + e1*ksumS[c0+1] + e2*ksumS[c0+8] + e3*ksumS[c0+9];
        }
        se += __shfl_xor_sync(0xffffffffu, se, 1);
        se += __shfl_xor_sync(0xffffffffu, se, 2);
        sd += __shfl_xor_sync(0xffffffffu, sd, 1);
        sd += __shfl_xor_sync(0xffffffffu, sd, 2);
        float scale = 1.f / (sd + 1e-6f*se);
        #pragma unroll
        for (int kt = 0; kt < 4; kt++) {
            split_pair(exr[kt*4+0]*scale, exr[kt*4+1]*scale, aEh[kt][ri],   aEl[kt][ri]);
            split_pair(exr[kt*4+2]*scale, exr[kt*4+3]*scale, aEh[kt][2+ri], aEl[kt][2+ri]);
        }
    }

    float o[8][4];
    #pragma unroll
    for (int a = 0; a < 8; a++)
        #pragma unroll
        for (int j = 0; j < 4; j++) o[a][j] = 0.f;

    // ---- linear-branch GEMM: o_l[16q x 64j] = Escaled[16 x 64d] @ kvW_t[j][d] ----
    CP_WAIT(0);
    __syncthreads();   // kvW smem ready
    {
        const uint32_t aWh = smem_u32(&sKh[0][0]) + (uint32_t)(rowoff*PADW + koff)*2;
        const uint32_t aWl = smem_u32(&sKl[0][0]) + (uint32_t)(rowoff*PADW + koff)*2;
        #pragma unroll
        for (int kt = 0; kt < 4; kt++) {
            #pragma unroll
            for (int nvp = 0; nvp < 4; nvp++) {
                uint32_t off = (uint32_t)(nvp*16*PADW + kt*16)*2;
                uint32_t h0,h1,h2,h3, l0,l1,l2,l3;
                ldmx4(h0,h1,h2,h3, aWh + off);
                ldmx4(l0,l1,l2,l3, aWl + off);
                mma16816(o[2*nvp],   aEh[kt], h0, h1);
                mma16816(o[2*nvp],   aEl[kt], h0, h1);
                mma16816(o[2*nvp],   aEh[kt], l0, l1);
                mma16816(o[2*nvp+1], aEh[kt], h2, h3);
                mma16816(o[2*nvp+1], aEl[kt], h2, h3);
                mma16816(o[2*nvp+1], aEh[kt], l2, l3);
            }
        }
    }
    // write o_l + bias, reset accumulators
    #pragma unroll
    for (int nv = 0; nv < 8; nv++) {
        int cc = nv*8 + tc*2;
        *(float2*)(out0 + cc) = make_float2(o[nv][0] + bS[cc], o[nv][1] + bS[cc+1]);
        *(float2*)(out1 + cc) = make_float2(o[nv][2] + bS[cc], o[nv][3] + bS[cc+1]);
        o[nv][0] = 0.f; o[nv][1] = 0.f; o[nv][2] = 0.f; o[nv][3] = 0.f;
    }
    __syncthreads();   // all warps done reading kvW smem before K loads overwrite it

    // ---- sparse mainloop ----
    const int krow = tid >> 2, kseg = tid & 3;
    const int vrow = tid >> 1, vseg = tid & 1;
    const uint32_t ksm = (uint32_t)(krow*PADK + kseg*16)*2;
    const uint32_t vsm = (uint32_t)(vrow*PADV + vseg*16)*2;
    const size_t   kgo = (size_t)krow*64 + kseg*16;
    const size_t   vgo = (size_t)vrow*32 + vseg*16;
    const int* lut = g_lut + (h*M + m)*T;

    #define LOAD_STAGE(n_, buf_) do { \
        size_t kb = ((size_t)(h*NBLK + (n_)))*2048 + kgo; \
        size_t vb = ((size_t)(h*NBLK + (n_)))*2048 + vgo; \
        uint32_t skh = smem_u32(&sKh[buf_][0]) + ksm; \
        uint32_t skl = smem_u32(&sKl[buf_][0]) + ksm; \
        uint32_t svh = smem_u32(&sVh[buf_][0]) + vsm; \
        uint32_t svl = smem_u32(&sVl[buf_][0]) + vsm; \
        cp16(skh,      g_kch + kb); \
        cp16(skh + 16, g_kch + kb + 8); \
        cp16(skl,      g_kcl + kb); \
        cp16(skl + 16, g_kcl + kb + 8); \
        cp16(svh,      g_vth + vb); \
        cp16(svh + 16, g_vth + vb + 8); \
        cp16(svl,      g_vtl + vb); \
        cp16(svl + 16, g_vtl + vb + 8); \
    } while (0)

    float lrow0 = 0.f, lrow1 = 0.f;

    LOAD_STAGE(lut[0], 0);
    CP_COMMIT();

    for (int t = 0; t < T; t++) {
        int buf = t & 1;
        if (t + 1 < T) {
            LOAD_STAGE(lut[t+1], (t+1) & 1);
            CP_COMMIT();
            CP_WAIT(1);
        } else {
            CP_WAIT(0);
        }
        __syncthreads();

        const uint32_t aKh = smem_u32(&sKh[buf][0]) + (uint32_t)(rowoff*PADK + koff)*2;
        const uint32_t aKl = smem_u32(&sKl[buf][0]) + (uint32_t)(rowoff*PADK + koff)*2;
        const uint32_t aVh = smem_u32(&sVh[buf][0]) + (uint32_t)(rowoff*PADV + koff)*2;
        const uint32_t aVl = smem_u32(&sVl[buf][0]) + (uint32_t)(rowoff*PADV + koff)*2;

        float c[4][4];
        #pragma unroll
        for (int nt = 0; nt < 4; nt++)
            #pragma unroll
            for (int j = 0; j < 4; j++) c[nt][j] = 0.f;
        #pragma unroll
        for (int ntp = 0; ntp < 2; ntp++) {
            #pragma unroll
            for (int kt = 0; kt < 4; kt++) {
                uint32_t off = (uint32_t)(ntp*16*PADK + kt*16)*2;
                uint32_t h0,h1,h2,h3, l0,l1,l2,l3;
                ldmx4(h0,h1,h2,h3, aKh + off);
                ldmx4(l0,l1,l2,l3, aKl + off);
                mma16816(c[2*ntp],   aQh[kt], h0, h1);
                mma16816(c[2*ntp],   aQl[kt], h0, h1);
                mma16816(c[2*ntp],   aQh[kt], l0, l1);
                mma16816(c[2*ntp+1], aQh[kt], h2, h3);
                mma16816(c[2*ntp+1], aQl[kt], h2, h3);
                mma16816(c[2*ntp+1], aQh[kt], l2, l3);
            }
        }
        float pr[4][4];
        float rs0 = 0.f, rs1 = 0.f;
        #pragma unroll
        for (int nt = 0; nt < 4; nt++) {
            #pragma unroll
            for (int j = 0; j < 4; j++) pr[nt][j] = __expf(c[nt][j] * 0.125f);
            rs0 += pr[nt][0] + pr[nt][1];
            rs1 += pr[nt][2] + pr[nt][3];
        }
        rs0 += __shfl_xor_sync(0xffffffffu, rs0, 1);
        rs0 += __shfl_xor_sync(0xffffffffu, rs0, 2);
        rs1 += __shfl_xor_sync(0xffffffffu, rs1, 1);
        rs1 += __shfl_xor_sync(0xffffffffu, rs1, 2);
        lrow0 += rs0; lrow1 += rs1;

        uint32_t aPh[2][4], aPl[2][4];
        #pragma unroll
        for (int kp2 = 0; kp2 < 2; kp2++) {
            split_pair(pr[2*kp2][0],   pr[2*kp2][1],   aPh[kp2][0], aPl[kp2][0]);
            split_pair(pr[2*kp2][2],   pr[2*kp2][3],   aPh[kp2][1], aPl[kp2][1]);
            split_pair(pr[2*kp2+1][0], pr[2*kp2+1][1], aPh[kp2][2], aPl[kp2][2]);
            split_pair(pr[2*kp2+1][2], pr[2*kp2+1][3], aPh[kp2][3], aPl[kp2][3]);
        }
        #pragma unroll
        for (int nvp = 0; nvp < 4; nvp++) {
            #pragma unroll
            for (int kp2 = 0; kp2 < 2; kp2++) {
                uint32_t off = (uint32_t)(nvp*16*PADV + kp2*16)*2;
                uint32_t h0,h1,h2,h3, l0,l1,l2,l3;
                ldmx4(h0,h1,h2,h3, aVh + off);
                ldmx4(l0,l1,l2,l3, aVl + off);
                mma16816(o[2*nvp],   aPh[kp2], h0, h1);
                mma16816(o[2*nvp],   aPl[kp2], h0, h1);
                mma16816(o[2*nvp],   aPh[kp2], l0, l1);
                mma16816(o[2*nvp+1], aPh[kp2], h2, h3);
                mma16816(o[2*nvp+1], aPl[kp2], h2, h3);
                mma16816(o[2*nvp+1], aPh[kp2], l2, l3);
            }
        }
        __syncthreads();
    }

    // ---- epilogue: out += o_s / lrow ----
    float inv0 = 1.f / lrow0;
    float inv1 = 1.f / lrow1;
    #pragma unroll
    for (int nv = 0; nv < 8; nv++) {
        int cc = nv*8 + tc*2;
        float2 p0 = *(float2*)(out0 + cc);
        float2 p1 = *(float2*)(out1 + cc);
        p0.x += o[nv][0]*inv0; p0.y += o[nv][1]*inv0;
        p1.x += o[nv][2]*inv1; p1.y += o[nv][3]*inv1;
        *(float2*)(out0 + cc) = p0;
        *(float2*)(out1 + cc) = p1;
    }
    #undef LOAD_STAGE
}

extern "C" void kernel_launch(void* const* d_in, const int* in_sizes, int n_in,
                              void* d_out, int out_size) {
    const float* q = (const float*)d_in[0];
    const float* k = (const float*)d_in[1];
    const float* v = (const float*)d_in[2];
    const float* W = (const float*)d_in[3];
    const float* b = (const float*)d_in[4];
    float* out = (float*)d_out;

    prep_kernel<<<dim3(H, M + NBLK), 256>>>(q, k);
    km_from_pk_kernel<<<H, 64>>>();
    scoretopk_kernel<<<dim3(H, M/16), 256>>>();
    convert_kv_kernel<<<dim3(H, NBLK), 128>>>(k, v);
    kvsum_partial_kernel<<<dim3(H, NCH), 256>>>(k, v);
    reduce_kv_kernel<<<H, 256>>>(W);
    sparse_attn_mma<<<dim3(H, M), 128>>>(q, b, out);
}